// round 14
// baseline (speedup 1.0000x reference)
#include <cuda_runtime.h>
#include <cuda_bf16.h>
#include <cstdint>

#define N_NODES 100000
#define E_EDGES 1280000
#define C_IN    64
#define MID     256
#define OUT_F   64
#define BN_EPS  1e-5f
#define NTILES  782            // ceil(100000/128)

// ---------------- scratch (static device memory; zero-init at load) --------
__device__ unsigned int g_zero[2 * N_NODES + 512];
#define P_CNT()    ((int*)g_zero)
#define P_OFF()    (((int*)g_zero) + N_NODES)
#define P_COLSUM() ((float*)(((int*)g_zero) + 2 * N_NODES))
#define P_COLSQ()  ((float*)(((int*)g_zero) + 2 * N_NODES + 256))

__device__ int   g_start[N_NODES + 1];            // CSR offsets
__device__ int2  g_edge[E_EDGES];                 // row-sorted (col, attr-bits)
__device__ __nv_bfloat16 g_Ahi[(size_t)N_NODES * 128];  // agg bf16 split
__device__ __nv_bfloat16 g_Alo[(size_t)N_NODES * 128];
__device__ __nv_bfloat16 g_Bhi[256 * 128];        // W1^T bf16 split [n][k]
__device__ __nv_bfloat16 g_Blo[256 * 128];
__device__ uint32_t g_hhi[(size_t)N_NODES * 128]; // h bf16 split, packed pairs
__device__ uint32_t g_hlo[(size_t)N_NODES * 128];
__device__ uint32_t g_W2phi[64 * 128];            // W2p^T bf16 split [n][k] pairs
__device__ uint32_t g_W2plo[64 * 128];
__device__ float g_b2p[OUT_F];

// ---------------- bf16 split helpers ---------------------------------------
__device__ __forceinline__ uint32_t packhi2(float v0, float v1) {
    __nv_bfloat162 h = __floats2bfloat162_rn(v0, v1);
    return *reinterpret_cast<uint32_t*>(&h);
}
__device__ __forceinline__ uint32_t packlo2(float v0, float v1) {
    float r0 = v0 - __bfloat162float(__float2bfloat16(v0));
    float r1 = v1 - __bfloat162float(__float2bfloat16(v1));
    __nv_bfloat162 l = __floats2bfloat162_rn(r0, r1);
    return *reinterpret_cast<uint32_t*>(&l);
}

// ---------------- mma.sync helpers (sm_80+ path) ----------------------------
__device__ __forceinline__ uint32_t smem_u32(const void* p) {
    uint32_t a;
    asm("{ .reg .u64 t; cvta.to.shared.u64 t, %1; cvt.u32.u64 %0, t; }"
        : "=r"(a) : "l"(p));
    return a;
}
#define LDSM_X4(r, addr) \
    asm volatile("ldmatrix.sync.aligned.m8n8.x4.shared.b16 {%0,%1,%2,%3}, [%4];" \
        : "=r"((r)[0]), "=r"((r)[1]), "=r"((r)[2]), "=r"((r)[3]) : "r"(addr))
#define MMA_BF16(d, a, b0, b1) \
    asm volatile("mma.sync.aligned.m16n8k16.row.col.f32.bf16.bf16.f32 " \
        "{%0,%1,%2,%3}, {%4,%5,%6,%7}, {%8,%9}, {%0,%1,%2,%3};" \
        : "+f"((d)[0]), "+f"((d)[1]), "+f"((d)[2]), "+f"((d)[3]) \
        : "r"((a)[0]), "r"((a)[1]), "r"((a)[2]), "r"((a)[3]), "r"(b0), "r"(b1))

// ---------------- per-block dtype detection --------------------------------
__device__ __forceinline__ int detect_idx64_block(const int* ei32, int* sflag) {
    if (threadIdx.x == 0) {
        int all_zero = 1;
        #pragma unroll
        for (int i = 0; i < 16; i++)
            if (ei32[2 * i + 1] != 0) all_zero = 0;
        *sflag = all_zero;
    }
    __syncthreads();
    return *sflag;
}
__device__ __forceinline__ int load_idx(const void* ei, size_t pos, int idx64) {
    return idx64 ? (int)((const long long*)ei)[pos] : ((const int*)ei)[pos];
}

// ---------------- 1) histogram ---------------------------------------------
__global__ void hist_kernel(const void* __restrict__ ei) {
    __shared__ int sflag;
    int idx64 = detect_idx64_block((const int*)ei, &sflag);
    int e = blockIdx.x * blockDim.x + threadIdx.x;
    if (e >= E_EDGES) return;
    int row = load_idx(ei, e, idx64);
    if ((unsigned)row < N_NODES) atomicAdd(&P_CNT()[row], 1);
}

// ---------------- 2) scan + W1 split-image build + colstat zero ------------
__global__ __launch_bounds__(1024)
void scan_kernel(const float* __restrict__ W1) {
    __shared__ int wsum[32], woff[32];
    __shared__ int carry_s, wtot_s;
    int tid = threadIdx.x, lane = tid & 31, wid = tid >> 5;
    if (tid == 0) carry_s = 0;
    if (tid < 256) { P_COLSUM()[tid] = 0.f; P_COLSQ()[tid] = 0.f; }
    __syncthreads();
    const int* cnt = P_CNT();
    #pragma unroll 1
    for (int c = 0; c < 25; c++) {
        int base = c * 4096 + tid * 4;
        int4 v;
        v.x = (base     < N_NODES) ? cnt[base]     : 0;
        v.y = (base + 1 < N_NODES) ? cnt[base + 1] : 0;
        v.z = (base + 2 < N_NODES) ? cnt[base + 2] : 0;
        v.w = (base + 3 < N_NODES) ? cnt[base + 3] : 0;
        int s = v.x + v.y + v.z + v.w;
        int p = s;
        #pragma unroll
        for (int o = 1; o < 32; o <<= 1) {
            int t = __shfl_up_sync(0xFFFFFFFFu, p, o);
            if (lane >= o) p += t;
        }
        if (lane == 31) wsum[wid] = p;
        __syncthreads();
        if (wid == 0) {
            int t = wsum[lane];
            int q = t;
            #pragma unroll
            for (int o = 1; o < 32; o <<= 1) {
                int u = __shfl_up_sync(0xFFFFFFFFu, q, o);
                if (lane >= o) q += u;
            }
            woff[lane] = q - t;
            if (lane == 31) wtot_s = q;
        }
        __syncthreads();
        int excl = carry_s + woff[wid] + (p - s);
        int e0 = excl, e1 = excl + v.x, e2 = e1 + v.y, e3 = e2 + v.z;
        if (base     < N_NODES) { g_start[base]     = e0; P_OFF()[base]     = e0; }
        if (base + 1 < N_NODES) { g_start[base + 1] = e1; P_OFF()[base + 1] = e1; }
        if (base + 2 < N_NODES) { g_start[base + 2] = e2; P_OFF()[base + 2] = e2; }
        if (base + 3 < N_NODES) { g_start[base + 3] = e3; P_OFF()[base + 3] = e3; }
        __syncthreads();
        if (tid == 0) carry_s += wtot_s;
        __syncthreads();
    }
    if (tid == 0) g_start[N_NODES] = carry_s;

    // W1^T split images: [n=256][k=128] bf16, stored as packed u32 k-pairs
    for (int idx = tid; idx < 16384; idx += 1024) {
        int n = idx >> 6, kp = idx & 63;
        float v0 = W1[(size_t)(2 * kp)     * MID + n];
        float v1 = W1[(size_t)(2 * kp + 1) * MID + n];
        ((uint32_t*)g_Bhi)[n * 64 + kp] = packhi2(v0, v1);
        ((uint32_t*)g_Blo)[n * 64 + kp] = packlo2(v0, v1);
    }
}

// ---------------- 3) scatter into row-sorted order -------------------------
__global__ void scatter_kernel(const void* __restrict__ ei,
                               const float* __restrict__ ea) {
    __shared__ int sflag;
    int idx64 = detect_idx64_block((const int*)ei, &sflag);
    int e = blockIdx.x * blockDim.x + threadIdx.x;
    if (e >= E_EDGES) return;
    int row = load_idx(ei, e, idx64);
    int col = load_idx(ei, (size_t)E_EDGES + e, idx64);
    if ((unsigned)row >= N_NODES || (unsigned)col >= N_NODES) return;
    int p = atomicAdd(&P_OFF()[row], 1);
    g_edge[p] = make_int2(col, __float_as_int(ea[e]));
}

// ---------------- 4) warp-per-node gather; float2 loads; bf16 split --------
// Lane handles features (2*lane, 2*lane+1): ONE LDG.64 per edge per lane.
__global__ __launch_bounds__(256)
void agg_kernel(const float* __restrict__ x) {
    int node = (blockIdx.x * blockDim.x + threadIdx.x) >> 5;
    int lane = threadIdx.x & 31;
    if (node >= N_NODES) return;
    int s = g_start[node];
    int e = g_start[node + 1];
    float vxa = 0.f, vya = 0.f, wxa = 0.f, wya = 0.f;
    float vxb = 0.f, vyb = 0.f, wxb = 0.f, wyb = 0.f;
    for (int base = s; base < e; base += 32) {
        int rem = e - base;
        int2 ed = make_int2(0, 0);
        if (lane < rem) ed = g_edge[base + lane];
        int n = rem < 32 ? rem : 32;
        int j = 0;
        #pragma unroll 1
        for (; j + 4 <= n; j += 4) {
            int   c0 = __shfl_sync(0xFFFFFFFFu, ed.x, j);
            float a0 = __int_as_float(__shfl_sync(0xFFFFFFFFu, ed.y, j));
            int   c1 = __shfl_sync(0xFFFFFFFFu, ed.x, j + 1);
            float a1 = __int_as_float(__shfl_sync(0xFFFFFFFFu, ed.y, j + 1));
            int   c2 = __shfl_sync(0xFFFFFFFFu, ed.x, j + 2);
            float a2 = __int_as_float(__shfl_sync(0xFFFFFFFFu, ed.y, j + 2));
            int   c3 = __shfl_sync(0xFFFFFFFFu, ed.x, j + 3);
            float a3 = __int_as_float(__shfl_sync(0xFFFFFFFFu, ed.y, j + 3));
            float2 p0 = *(const float2*)(x + (size_t)c0 * C_IN + 2 * lane);
            float2 p1 = *(const float2*)(x + (size_t)c1 * C_IN + 2 * lane);
            float2 p2 = *(const float2*)(x + (size_t)c2 * C_IN + 2 * lane);
            float2 p3 = *(const float2*)(x + (size_t)c3 * C_IN + 2 * lane);
            vxa += p0.x; vya += p0.y; wxa = fmaf(p0.x, a0, wxa); wya = fmaf(p0.y, a0, wya);
            vxb += p1.x; vyb += p1.y; wxb = fmaf(p1.x, a1, wxb); wyb = fmaf(p1.y, a1, wyb);
            vxa += p2.x; vya += p2.y; wxa = fmaf(p2.x, a2, wxa); wya = fmaf(p2.y, a2, wya);
            vxb += p3.x; vyb += p3.y; wxb = fmaf(p3.x, a3, wxb); wyb = fmaf(p3.y, a3, wyb);
        }
        #pragma unroll 1
        for (; j < n; j++) {
            int   c = __shfl_sync(0xFFFFFFFFu, ed.x, j);
            float a = __int_as_float(__shfl_sync(0xFFFFFFFFu, ed.y, j));
            float2 p = *(const float2*)(x + (size_t)c * C_IN + 2 * lane);
            vxa += p.x; vya += p.y;
            wxa = fmaf(p.x, a, wxa); wya = fmaf(p.y, a, wya);
        }
    }
    float inv = 1.f / fmaxf((float)(e - s), 1.f);
    float vx = (vxa + vxb) * inv, vy = (vya + vyb) * inv;
    float wx = (wxa + wxb) * inv, wy = (wya + wyb) * inv;
    uint32_t* ahi = (uint32_t*)g_Ahi;
    uint32_t* alo = (uint32_t*)g_Alo;
    size_t base = (size_t)node * 64;
    ahi[base + lane]      = packhi2(vx, vy);
    alo[base + lane]      = packlo2(vx, vy);
    ahi[base + 32 + lane] = packhi2(wx, wy);
    alo[base + 32 + lane] = packlo2(wx, wy);
}

// ---------------- 5) GEMM1 via mma.sync bf16x3 + fused BN stats ------------
// 128m x 128n block (grid 782 x 2), 16 warps (4m x 4n), warp tile 32x32.
// Register-prefetched K-chunk staging: next chunk's LDGs issue before the
// current chunk's MMA loop. Same pitch-44 smem images (88 KB), 2 blocks/SM.
#define G1_SMEM_BYTES 90112
__global__ __launch_bounds__(512, 2)
void gemm1_tc(const float* __restrict__ b1g) {
    extern __shared__ __align__(16) uint32_t sm32[];
    uint32_t sb = smem_u32(sm32);
    __shared__ float ssum[128], ssq[128];
    int tid = threadIdx.x;
    int wid = tid >> 5, lane = tid & 31;
    int rowbase = blockIdx.x * 128;
    int nh = blockIdx.y;
    int warpM = wid & 3, warpN = wid >> 2;      // 4 x 4

    if (tid < 128) {
        ssum[tid] = 0.f; ssq[tid] = 0.f;
        int r = rowbase + tid;
        if (r < N_NODES) P_CNT()[r] = 0;    // re-zero for next graph replay
    }

    const uint4* gA4hi = (const uint4*)g_Ahi;
    const uint4* gA4lo = (const uint4*)g_Alo;
    const uint4* gB4hi = (const uint4*)g_Bhi;
    const uint4* gB4lo = (const uint4*)g_Blo;

    uint4 rAhi[2], rAlo[2], rBhi[2], rBlo[2];
#define G1_LOAD(kq4) \
    _Pragma("unroll") \
    for (int i = 0; i < 2; i++) { \
        int idx4 = i * 512 + tid; \
        int m = idx4 >> 3, kq = idx4 & 7; \
        int r = rowbase + m; \
        rAhi[i] = make_uint4(0, 0, 0, 0); rAlo[i] = make_uint4(0, 0, 0, 0); \
        if (r < N_NODES) { \
            rAhi[i] = gA4hi[(size_t)r * 16 + (kq4) + kq]; \
            rAlo[i] = gA4lo[(size_t)r * 16 + (kq4) + kq]; \
        } \
        int nrow = nh * 128 + m; \
        rBhi[i] = gB4hi[nrow * 16 + (kq4) + kq]; \
        rBlo[i] = gB4lo[nrow * 16 + (kq4) + kq]; \
    }
#define G1_STORE() \
    _Pragma("unroll") \
    for (int i = 0; i < 2; i++) { \
        int idx4 = i * 512 + tid; \
        int m = idx4 >> 3, kq = idx4 & 7; \
        *(uint4*)&sm32[m * 44 + kq * 4]         = rAhi[i]; \
        *(uint4*)&sm32[5632 + m * 44 + kq * 4]  = rAlo[i]; \
        *(uint4*)&sm32[11264 + m * 44 + kq * 4] = rBhi[i]; \
        *(uint4*)&sm32[16896 + m * 44 + kq * 4] = rBlo[i]; \
    }

    float acc[2][4][4];
    #pragma unroll
    for (int a = 0; a < 2; a++)
        #pragma unroll
        for (int b = 0; b < 4; b++)
            #pragma unroll
            for (int c = 0; c < 4; c++) acc[a][b][c] = 0.f;

    G1_LOAD(0);
    #pragma unroll 1
    for (int c = 0; c < 2; c++) {
        __syncthreads();
        G1_STORE();
        __syncthreads();
        if (c == 0) G1_LOAD(8);      // prefetch chunk 1 under chunk-0 MMA
        #pragma unroll
        for (int ks = 0; ks < 4; ks++) {
            uint32_t a_hi[2][4], a_lo[2][4], b[2][4], bds[2];
            int arow = (lane & 7) + ((lane >> 3) & 1) * 8;
            int akoff = ks * 16 + (lane >> 4) * 8;      // bf16 units
            #pragma unroll
            for (int mf = 0; mf < 2; mf++) {
                uint32_t ad = sb + (warpM * 32 + mf * 16 + arow) * 176 + akoff * 2;
                LDSM_X4(a_hi[mf], ad);
                LDSM_X4(a_lo[mf], ad + 22528);
            }
            int brow = (lane & 7) + (lane >> 4) * 8;
            int bkoff = ks * 16 + ((lane >> 3) & 1) * 8;
            #pragma unroll
            for (int nf = 0; nf < 2; nf++) {
                bds[nf] = sb + 45056 + (warpN * 32 + nf * 16 + brow) * 176 + bkoff * 2;
                LDSM_X4(b[nf], bds[nf]);
            }
            #pragma unroll
            for (int mf = 0; mf < 2; mf++)
                #pragma unroll
                for (int nf = 0; nf < 2; nf++) {
                    MMA_BF16(acc[mf][nf * 2],     a_hi[mf], b[nf][0], b[nf][1]);
                    MMA_BF16(acc[mf][nf * 2 + 1], a_hi[mf], b[nf][2], b[nf][3]);
                    MMA_BF16(acc[mf][nf * 2],     a_lo[mf], b[nf][0], b[nf][1]);
                    MMA_BF16(acc[mf][nf * 2 + 1], a_lo[mf], b[nf][2], b[nf][3]);
                }
            #pragma unroll
            for (int nf = 0; nf < 2; nf++) LDSM_X4(b[nf], bds[nf] + 22528);
            #pragma unroll
            for (int mf = 0; mf < 2; mf++)
                #pragma unroll
                for (int nf = 0; nf < 2; nf++) {
                    MMA_BF16(acc[mf][nf * 2],     a_hi[mf], b[nf][0], b[nf][1]);
                    MMA_BF16(acc[mf][nf * 2 + 1], a_hi[mf], b[nf][2], b[nf][3]);
                }
        }
    }

    // epilogue: +b1, relu, split-store h, BN stats
    float ls[4][2], lq[4][2];
    #pragma unroll
    for (int i = 0; i < 4; i++) { ls[i][0] = ls[i][1] = lq[i][0] = lq[i][1] = 0.f; }
    int mrow = rowbase + warpM * 32 + (lane >> 2);
    #pragma unroll
    for (int nfi = 0; nfi < 4; nfi++) {
        int nl = warpN * 32 + nfi * 8 + 2 * (lane & 3);
        int ncol = nh * 128 + nl;
        float bb0 = b1g[ncol], bb1 = b1g[ncol + 1];
        #pragma unroll
        for (int mf = 0; mf < 2; mf++) {
            int m0 = mrow + mf * 16;
            float v0 = fmaxf(acc[mf][nfi][0] + bb0, 0.f);
            float v1 = fmaxf(acc[mf][nfi][1] + bb1, 0.f);
            float v2 = fmaxf(acc[mf][nfi][2] + bb0, 0.f);
            float v3 = fmaxf(acc[mf][nfi][3] + bb1, 0.f);
            if (m0 < N_NODES) {
                g_hhi[(size_t)m0 * 128 + (ncol >> 1)] = packhi2(v0, v1);
                g_hlo[(size_t)m0 * 128 + (ncol >> 1)] = packlo2(v0, v1);
                ls[nfi][0] += v0; ls[nfi][1] += v1;
                lq[nfi][0] += v0 * v0; lq[nfi][1] += v1 * v1;
            }
            if (m0 + 8 < N_NODES) {
                g_hhi[(size_t)(m0 + 8) * 128 + (ncol >> 1)] = packhi2(v2, v3);
                g_hlo[(size_t)(m0 + 8) * 128 + (ncol >> 1)] = packlo2(v2, v3);
                ls[nfi][0] += v2; ls[nfi][1] += v3;
                lq[nfi][0] += v2 * v2; lq[nfi][1] += v3 * v3;
            }
        }
    }
    #pragma unroll
    for (int nfi = 0; nfi < 4; nfi++)
        #pragma unroll
        for (int j = 0; j < 2; j++) {
            float s = ls[nfi][j], q = lq[nfi][j];
            s += __shfl_xor_sync(0xFFFFFFFFu, s, 4);
            s += __shfl_xor_sync(0xFFFFFFFFu, s, 8);
            s += __shfl_xor_sync(0xFFFFFFFFu, s, 16);
            q += __shfl_xor_sync(0xFFFFFFFFu, q, 4);
            q += __shfl_xor_sync(0xFFFFFFFFu, q, 8);
            q += __shfl_xor_sync(0xFFFFFFFFu, q, 16);
            if ((lane >> 2) == 0) {
                int col = warpN * 32 + nfi * 8 + 2 * (lane & 3) + j;
                atomicAdd(&ssum[col], s);
                atomicAdd(&ssq[col], q);
            }
        }
    __syncthreads();
    if (tid < 128) {
        atomicAdd(&P_COLSUM()[nh * 128 + tid], ssum[tid]);
        atomicAdd(&P_COLSQ()[nh * 128 + tid],  ssq[tid]);
    }
}

// ---------------- 6) finalize: BN fold -> split W2p + b2' ------------------
__global__ void finalize_kernel(const float* __restrict__ gamma,
                                const float* __restrict__ beta,
                                const float* __restrict__ W2,
                                const float* __restrict__ b2) {
    __shared__ float s_sm[MID], t_sm[MID];
    int tid = threadIdx.x;  // 256
    float mu  = P_COLSUM()[tid] * (1.f / N_NODES);
    float var = P_COLSQ()[tid]  * (1.f / N_NODES) - mu * mu;
    float s = gamma[tid] * rsqrtf(var + BN_EPS);
    float t = beta[tid] - mu * s;
    s_sm[tid] = s; t_sm[tid] = t;
    __syncthreads();
    #pragma unroll 1
    for (int i = 0; i < 32; i++) {
        int idx = i * 256 + tid;            // 8192 k-pairs
        int n = idx >> 7, kp = idx & 127;
        float v0 = W2[(size_t)(2 * kp)     * OUT_F + n] * s_sm[2 * kp];
        float v1 = W2[(size_t)(2 * kp + 1) * OUT_F + n] * s_sm[2 * kp + 1];
        g_W2phi[n * 128 + kp] = packhi2(v0, v1);
        g_W2plo[n * 128 + kp] = packlo2(v0, v1);
    }
    if (tid < OUT_F) {
        float acc = b2[tid];
        for (int j = 0; j < MID; j++) acc += t_sm[j] * W2[j * OUT_F + tid];
        g_b2p[tid] = acc;
    }
}

// ---------------- 7) GEMM2 via mma.sync bf16x3 -----------------------------
// 128m x 64n block (grid 782), 16 warps (4m x 4n), warp tile 32x16.
// Register-prefetched staging across 4 K-chunks. smem 66 KB, 3 blocks/SM.
#define G2_SMEM_BYTES 67584
__global__ __launch_bounds__(512, 3)
void gemm2_tc(float* __restrict__ out) {
    extern __shared__ __align__(16) uint32_t sm32[];
    uint32_t sb = smem_u32(sm32);
    int tid = threadIdx.x;
    int wid = tid >> 5, lane = tid & 31;
    int rowbase = blockIdx.x * 128;
    int warpM = wid & 3, warpN = wid >> 2;      // 4 x 4

    const uint4* gh4hi = (const uint4*)g_hhi;
    const uint4* gh4lo = (const uint4*)g_hlo;
    const uint4* gW4hi = (const uint4*)g_W2phi;
    const uint4* gW4lo = (const uint4*)g_W2plo;

    uint4 rAhi[2], rAlo[2], rBhi, rBlo;
#define G2_LOAD(kq4) \
    _Pragma("unroll") \
    for (int i = 0; i < 2; i++) { \
        int idx4 = i * 512 + tid; \
        int m = idx4 >> 3, kq = idx4 & 7; \
        int r = rowbase + m; \
        rAhi[i] = make_uint4(0, 0, 0, 0); rAlo[i] = make_uint4(0, 0, 0, 0); \
        if (r < N_NODES) { \
            rAhi[i] = gh4hi[(size_t)r * 32 + (kq4) + kq]; \
            rAlo[i] = gh4lo[(size_t)r * 32 + (kq4) + kq]; \
        } \
    } \
    { \
        int n = tid >> 3, kq = tid & 7; \
        rBhi = gW4hi[n * 32 + (kq4) + kq]; \
        rBlo = gW4lo[n * 32 + (kq4) + kq]; \
    }
#define G2_STORE() \
    _Pragma("unroll") \
    for (int i = 0; i < 2; i++) { \
        int idx4 = i * 512 + tid; \
        int m = idx4 >> 3, kq = idx4 & 7; \
        *(uint4*)&sm32[m * 44 + kq * 4]        = rAhi[i]; \
        *(uint4*)&sm32[5632 + m * 44 + kq * 4] = rAlo[i]; \
    } \
    { \
        int n = tid >> 3, kq = tid & 7; \
        *(uint4*)&sm32[11264 + n * 44 + kq * 4] = rBhi; \
        *(uint4*)&sm32[14080 + n * 44 + kq * 4] = rBlo; \
    }

    float acc[2][2][4];
    #pragma unroll
    for (int a = 0; a < 2; a++)
        #pragma unroll
        for (int b = 0; b < 2; b++)
            #pragma unroll
            for (int c = 0; c < 4; c++) acc[a][b][c] = 0.f;

    G2_LOAD(0);
    #pragma unroll 1
    for (int c = 0; c < 4; c++) {
        __syncthreads();
        G2_STORE();
        __syncthreads();
        if (c < 3) G2_LOAD((c + 1) * 8);   // prefetch next chunk under MMA
        #pragma unroll
        for (int ks = 0; ks < 4; ks++) {
            uint32_t a_hi[2][4], a_lo[2][4], b[1][4], bds;
            int arow = (lane & 7) + ((lane >> 3) & 1) * 8;
            int akoff = ks * 16 + (lane >> 4) * 8;
            #pragma unroll
            for (int mf = 0; mf < 2; mf++) {
                uint32_t ad = sb + (warpM * 32 + mf * 16 + arow) * 176 + akoff * 2;
                LDSM_X4(a_hi[mf], ad);
                LDSM_X4(a_lo[mf], ad + 22528);
            }
            int brow = (lane & 7) + (lane >> 4) * 8;
            int bkoff = ks * 16 + ((lane >> 3) & 1) * 8;
            bds = sb + 45056 + (warpN * 16 + brow) * 176 + bkoff * 2;
            LDSM_X4(b[0], bds);
            #pragma unroll
            for (int mf = 0; mf < 2; mf++) {
                MMA_BF16(acc[mf][0], a_hi[mf], b[0][0], b[0][1]);
                MMA_BF16(acc[mf][1], a_hi[mf], b[0][2], b[0][3]);
                MMA_BF16(acc[mf][0], a_lo[mf], b[0][0], b[0][1]);
                MMA_BF16(acc[mf][1], a_lo[mf], b[0][2], b[0][3]);
            }
            LDSM_X4(b[0], bds + 11264);
            #pragma unroll
            for (int mf = 0; mf < 2; mf++) {
                MMA_BF16(acc[mf][0], a_hi[mf], b[0][0], b[0][1]);
                MMA_BF16(acc[mf][1], a_hi[mf], b[0][2], b[0][3]);
            }
        }
    }

    int mrow = rowbase + warpM * 32 + (lane >> 2);
    #pragma unroll
    for (int nfi = 0; nfi < 2; nfi++) {
        int nl = warpN * 16 + nfi * 8 + 2 * (lane & 3);
        float bb0 = g_b2p[nl], bb1 = g_b2p[nl + 1];
        #pragma unroll
        for (int mf = 0; mf < 2; mf++) {
            int m0 = mrow + mf * 16;
            if (m0 < N_NODES) {
                float2 o = make_float2(acc[mf][nfi][0] + bb0, acc[mf][nfi][1] + bb1);
                *(float2*)&out[(size_t)m0 * OUT_F + nl] = o;
            }
            if (m0 + 8 < N_NODES) {
                float2 o = make_float2(acc[mf][nfi][2] + bb0, acc[mf][nfi][3] + bb1);
                *(float2*)&out[(size_t)(m0 + 8) * OUT_F + nl] = o;
            }
        }
    }
}

// ---------------- launch ---------------------------------------------------
extern "C" void kernel_launch(void* const* d_in, const int* in_sizes, int n_in,
                              void* d_out, int out_size) {
    int ix = -1, iei = -1, iea = -1, iW1 = -1, iW2 = -1, ib2 = -1;
    int p256[3]; int n256 = 0;
    for (int i = 0; i < n_in; i++) {
        switch (in_sizes[i]) {
            case 6400000: ix  = i; break;
            case 2560000: iei = i; break;
            case 1280000: iea = i; break;
            case 32768:   iW1 = i; break;
            case 16384:   iW2 = i; break;
            case 64:      ib2 = i; break;
            case 256:     if (n256 < 3) p256[n256++] = i; break;
            default: break;
        }
    }
    int ib1, igamma, ibeta;
    if (n_in > 0 && in_sizes[0] == 6400000) { ib1 = p256[0]; igamma = p256[1]; ibeta = p256[2]; }
    else                                    { ib1 = p256[0]; ibeta  = p256[1]; igamma = p256[2]; }

    const float* x     = (const float*)d_in[ix];
    const void*  ei    = d_in[iei];
    const float* ea    = (const float*)d_in[iea];
    const float* W1    = (const float*)d_in[iW1];
    const float* b1    = (const float*)d_in[ib1];
    const float* gamma = (const float*)d_in[igamma];
    const float* beta  = (const float*)d_in[ibeta];
    const float* W2    = (const float*)d_in[iW2];
    const float* b2    = (const float*)d_in[ib2];
    float* out = (float*)d_out;

    cudaFuncSetAttribute(gemm1_tc, cudaFuncAttributeMaxDynamicSharedMemorySize,
                         G1_SMEM_BYTES);
    cudaFuncSetAttribute(gemm2_tc, cudaFuncAttributeMaxDynamicSharedMemorySize,
                         G2_SMEM_BYTES);

    hist_kernel<<<(E_EDGES + 255) / 256, 256>>>(ei);
    scan_kernel<<<1, 1024>>>(W1);
    scatter_kernel<<<(E_EDGES + 255) / 256, 256>>>(ei, ea);
    agg_kernel<<<(N_NODES * 32 + 255) / 256, 256>>>(x);

    dim3 g1(NTILES, 2);
    gemm1_tc<<<g1, 512, G1_SMEM_BYTES>>>(b1);
    finalize_kernel<<<1, 256>>>(gamma, beta, W2, b2);
    gemm2_tc<<<NTILES, 512, G2_SMEM_BYTES>>>(out);
}

// round 15
// speedup vs baseline: 1.1721x; 1.1721x over previous
#include <cuda_runtime.h>
#include <cuda_bf16.h>
#include <cstdint>

#define N_NODES 100000
#define E_EDGES 1280000
#define C_IN    64
#define MID     256
#define OUT_F   64
#define BN_EPS  1e-5f
#define NTILES  782            // ceil(100000/128)

// ---------------- scratch (static device memory; zero-init at load) --------
__device__ unsigned int g_zero[2 * N_NODES + 512];
#define P_CNT()    ((int*)g_zero)
#define P_OFF()    (((int*)g_zero) + N_NODES)
#define P_COLSUM() ((float*)(((int*)g_zero) + 2 * N_NODES))
#define P_COLSQ()  ((float*)(((int*)g_zero) + 2 * N_NODES + 256))

__device__ int   g_start[N_NODES + 1];            // CSR offsets
__device__ int2  g_edge[E_EDGES];                 // row-sorted (col, attr-bits)
__device__ __nv_bfloat16 g_Ahi[(size_t)N_NODES * 128];  // agg bf16 split
__device__ __nv_bfloat16 g_Alo[(size_t)N_NODES * 128];
__device__ __nv_bfloat16 g_Bhi[256 * 128];        // W1^T bf16 split [n][k]
__device__ __nv_bfloat16 g_Blo[256 * 128];
__device__ uint32_t g_hhi[(size_t)N_NODES * 128]; // h bf16 split, packed pairs
__device__ uint32_t g_hlo[(size_t)N_NODES * 128];
__device__ uint32_t g_W2phi[64 * 128];            // W2p^T bf16 split [n][k] pairs
__device__ uint32_t g_W2plo[64 * 128];
__device__ float g_b2p[OUT_F];

// ---------------- bf16 split helpers ---------------------------------------
__device__ __forceinline__ uint32_t packhi2(float v0, float v1) {
    __nv_bfloat162 h = __floats2bfloat162_rn(v0, v1);
    return *reinterpret_cast<uint32_t*>(&h);
}
__device__ __forceinline__ uint32_t packlo2(float v0, float v1) {
    float r0 = v0 - __bfloat162float(__float2bfloat16(v0));
    float r1 = v1 - __bfloat162float(__float2bfloat16(v1));
    __nv_bfloat162 l = __floats2bfloat162_rn(r0, r1);
    return *reinterpret_cast<uint32_t*>(&l);
}

// ---------------- mma.sync helpers (sm_80+ path) ----------------------------
__device__ __forceinline__ uint32_t smem_u32(const void* p) {
    uint32_t a;
    asm("{ .reg .u64 t; cvta.to.shared.u64 t, %1; cvt.u32.u64 %0, t; }"
        : "=r"(a) : "l"(p));
    return a;
}
#define LDSM_X4(r, addr) \
    asm volatile("ldmatrix.sync.aligned.m8n8.x4.shared.b16 {%0,%1,%2,%3}, [%4];" \
        : "=r"((r)[0]), "=r"((r)[1]), "=r"((r)[2]), "=r"((r)[3]) : "r"(addr))
#define MMA_BF16(d, a, b0, b1) \
    asm volatile("mma.sync.aligned.m16n8k16.row.col.f32.bf16.bf16.f32 " \
        "{%0,%1,%2,%3}, {%4,%5,%6,%7}, {%8,%9}, {%0,%1,%2,%3};" \
        : "+f"((d)[0]), "+f"((d)[1]), "+f"((d)[2]), "+f"((d)[3]) \
        : "r"((a)[0]), "r"((a)[1]), "r"((a)[2]), "r"((a)[3]), "r"(b0), "r"(b1))

// ---------------- per-block dtype detection --------------------------------
__device__ __forceinline__ int detect_idx64_block(const int* ei32, int* sflag) {
    if (threadIdx.x == 0) {
        int all_zero = 1;
        #pragma unroll
        for (int i = 0; i < 16; i++)
            if (ei32[2 * i + 1] != 0) all_zero = 0;
        *sflag = all_zero;
    }
    __syncthreads();
    return *sflag;
}
__device__ __forceinline__ int load_idx(const void* ei, size_t pos, int idx64) {
    return idx64 ? (int)((const long long*)ei)[pos] : ((const int*)ei)[pos];
}

// ---------------- 1) histogram ---------------------------------------------
__global__ void hist_kernel(const void* __restrict__ ei) {
    __shared__ int sflag;
    int idx64 = detect_idx64_block((const int*)ei, &sflag);
    int e = blockIdx.x * blockDim.x + threadIdx.x;
    if (e >= E_EDGES) return;
    int row = load_idx(ei, e, idx64);
    if ((unsigned)row < N_NODES) atomicAdd(&P_CNT()[row], 1);
}

// ---------------- 2) scan + W1 split-image build + colstat zero ------------
__global__ __launch_bounds__(1024)
void scan_kernel(const float* __restrict__ W1) {
    __shared__ int wsum[32], woff[32];
    __shared__ int carry_s, wtot_s;
    int tid = threadIdx.x, lane = tid & 31, wid = tid >> 5;
    if (tid == 0) carry_s = 0;
    if (tid < 256) { P_COLSUM()[tid] = 0.f; P_COLSQ()[tid] = 0.f; }
    __syncthreads();
    const int* cnt = P_CNT();
    #pragma unroll 1
    for (int c = 0; c < 25; c++) {
        int base = c * 4096 + tid * 4;
        int4 v;
        v.x = (base     < N_NODES) ? cnt[base]     : 0;
        v.y = (base + 1 < N_NODES) ? cnt[base + 1] : 0;
        v.z = (base + 2 < N_NODES) ? cnt[base + 2] : 0;
        v.w = (base + 3 < N_NODES) ? cnt[base + 3] : 0;
        int s = v.x + v.y + v.z + v.w;
        int p = s;
        #pragma unroll
        for (int o = 1; o < 32; o <<= 1) {
            int t = __shfl_up_sync(0xFFFFFFFFu, p, o);
            if (lane >= o) p += t;
        }
        if (lane == 31) wsum[wid] = p;
        __syncthreads();
        if (wid == 0) {
            int t = wsum[lane];
            int q = t;
            #pragma unroll
            for (int o = 1; o < 32; o <<= 1) {
                int u = __shfl_up_sync(0xFFFFFFFFu, q, o);
                if (lane >= o) q += u;
            }
            woff[lane] = q - t;
            if (lane == 31) wtot_s = q;
        }
        __syncthreads();
        int excl = carry_s + woff[wid] + (p - s);
        int e0 = excl, e1 = excl + v.x, e2 = e1 + v.y, e3 = e2 + v.z;
        if (base     < N_NODES) { g_start[base]     = e0; P_OFF()[base]     = e0; }
        if (base + 1 < N_NODES) { g_start[base + 1] = e1; P_OFF()[base + 1] = e1; }
        if (base + 2 < N_NODES) { g_start[base + 2] = e2; P_OFF()[base + 2] = e2; }
        if (base + 3 < N_NODES) { g_start[base + 3] = e3; P_OFF()[base + 3] = e3; }
        __syncthreads();
        if (tid == 0) carry_s += wtot_s;
        __syncthreads();
    }
    if (tid == 0) g_start[N_NODES] = carry_s;

    // W1^T split images: [n=256][k=128] bf16, stored as packed u32 k-pairs
    for (int idx = tid; idx < 16384; idx += 1024) {
        int n = idx >> 6, kp = idx & 63;
        float v0 = W1[(size_t)(2 * kp)     * MID + n];
        float v1 = W1[(size_t)(2 * kp + 1) * MID + n];
        ((uint32_t*)g_Bhi)[n * 64 + kp] = packhi2(v0, v1);
        ((uint32_t*)g_Blo)[n * 64 + kp] = packlo2(v0, v1);
    }
}

// ---------------- 3) scatter into row-sorted order -------------------------
__global__ void scatter_kernel(const void* __restrict__ ei,
                               const float* __restrict__ ea) {
    __shared__ int sflag;
    int idx64 = detect_idx64_block((const int*)ei, &sflag);
    int e = blockIdx.x * blockDim.x + threadIdx.x;
    if (e >= E_EDGES) return;
    int row = load_idx(ei, e, idx64);
    int col = load_idx(ei, (size_t)E_EDGES + e, idx64);
    if ((unsigned)row >= N_NODES || (unsigned)col >= N_NODES) return;
    int p = atomicAdd(&P_OFF()[row], 1);
    g_edge[p] = make_int2(col, __float_as_int(ea[e]));
}

// ---------------- 4) warp-per-node gather; float2 loads; bf16 split --------
// Lane handles features (2*lane, 2*lane+1): ONE LDG.64 per edge per lane.
__global__ __launch_bounds__(256)
void agg_kernel(const float* __restrict__ x) {
    int node = (blockIdx.x * blockDim.x + threadIdx.x) >> 5;
    int lane = threadIdx.x & 31;
    if (node >= N_NODES) return;
    int s = g_start[node];
    int e = g_start[node + 1];
    float vxa = 0.f, vya = 0.f, wxa = 0.f, wya = 0.f;
    float vxb = 0.f, vyb = 0.f, wxb = 0.f, wyb = 0.f;
    for (int base = s; base < e; base += 32) {
        int rem = e - base;
        int2 ed = make_int2(0, 0);
        if (lane < rem) ed = g_edge[base + lane];
        int n = rem < 32 ? rem : 32;
        int j = 0;
        #pragma unroll 1
        for (; j + 4 <= n; j += 4) {
            int   c0 = __shfl_sync(0xFFFFFFFFu, ed.x, j);
            float a0 = __int_as_float(__shfl_sync(0xFFFFFFFFu, ed.y, j));
            int   c1 = __shfl_sync(0xFFFFFFFFu, ed.x, j + 1);
            float a1 = __int_as_float(__shfl_sync(0xFFFFFFFFu, ed.y, j + 1));
            int   c2 = __shfl_sync(0xFFFFFFFFu, ed.x, j + 2);
            float a2 = __int_as_float(__shfl_sync(0xFFFFFFFFu, ed.y, j + 2));
            int   c3 = __shfl_sync(0xFFFFFFFFu, ed.x, j + 3);
            float a3 = __int_as_float(__shfl_sync(0xFFFFFFFFu, ed.y, j + 3));
            float2 p0 = *(const float2*)(x + (size_t)c0 * C_IN + 2 * lane);
            float2 p1 = *(const float2*)(x + (size_t)c1 * C_IN + 2 * lane);
            float2 p2 = *(const float2*)(x + (size_t)c2 * C_IN + 2 * lane);
            float2 p3 = *(const float2*)(x + (size_t)c3 * C_IN + 2 * lane);
            vxa += p0.x; vya += p0.y; wxa = fmaf(p0.x, a0, wxa); wya = fmaf(p0.y, a0, wya);
            vxb += p1.x; vyb += p1.y; wxb = fmaf(p1.x, a1, wxb); wyb = fmaf(p1.y, a1, wyb);
            vxa += p2.x; vya += p2.y; wxa = fmaf(p2.x, a2, wxa); wya = fmaf(p2.y, a2, wya);
            vxb += p3.x; vyb += p3.y; wxb = fmaf(p3.x, a3, wxb); wyb = fmaf(p3.y, a3, wyb);
        }
        #pragma unroll 1
        for (; j < n; j++) {
            int   c = __shfl_sync(0xFFFFFFFFu, ed.x, j);
            float a = __int_as_float(__shfl_sync(0xFFFFFFFFu, ed.y, j));
            float2 p = *(const float2*)(x + (size_t)c * C_IN + 2 * lane);
            vxa += p.x; vya += p.y;
            wxa = fmaf(p.x, a, wxa); wya = fmaf(p.y, a, wya);
        }
    }
    float inv = 1.f / fmaxf((float)(e - s), 1.f);
    float vx = (vxa + vxb) * inv, vy = (vya + vyb) * inv;
    float wx = (wxa + wxb) * inv, wy = (wya + wyb) * inv;
    uint32_t* ahi = (uint32_t*)g_Ahi;
    uint32_t* alo = (uint32_t*)g_Alo;
    size_t base = (size_t)node * 64;
    ahi[base + lane]      = packhi2(vx, vy);
    alo[base + lane]      = packlo2(vx, vy);
    ahi[base + 32 + lane] = packhi2(wx, wy);
    alo[base + 32 + lane] = packlo2(wx, wy);
}

// ---------------- 5) GEMM1 via mma.sync bf16x3 + fused BN stats ------------
// 128m x 128n block (grid 782 x 2), 16 warps (4m x 4n), warp tile 32x32.
// Same pitch-44 smem images (88 KB), 2 blocks/SM -> 8 warps/SMSP. (R13 form)
#define G1_SMEM_BYTES 90112
__global__ __launch_bounds__(512, 2)
void gemm1_tc(const float* __restrict__ b1g) {
    extern __shared__ __align__(16) uint32_t sm32[];
    uint32_t sb = smem_u32(sm32);
    __shared__ float ssum[128], ssq[128];
    int tid = threadIdx.x;
    int wid = tid >> 5, lane = tid & 31;
    int rowbase = blockIdx.x * 128;
    int nh = blockIdx.y;
    int warpM = wid & 3, warpN = wid >> 2;      // 4 x 4

    if (tid < 128) {
        ssum[tid] = 0.f; ssq[tid] = 0.f;
        int r = rowbase + tid;
        if (r < N_NODES) P_CNT()[r] = 0;    // re-zero for next graph replay
    }

    const uint4* gA4hi = (const uint4*)g_Ahi;
    const uint4* gA4lo = (const uint4*)g_Alo;
    const uint4* gB4hi = (const uint4*)g_Bhi;
    const uint4* gB4lo = (const uint4*)g_Blo;

    float acc[2][4][4];
    #pragma unroll
    for (int a = 0; a < 2; a++)
        #pragma unroll
        for (int b = 0; b < 4; b++)
            #pragma unroll
            for (int c = 0; c < 4; c++) acc[a][b][c] = 0.f;

    #pragma unroll 1
    for (int kc2 = 0; kc2 < 64; kc2 += 32) {    // k-pair (u32) chunk offset
        int kq4 = kc2 >> 2;                      // uint4 offset {0, 8}
        __syncthreads();
        #pragma unroll
        for (int i = 0; i < 2; i++) {
            int idx4 = i * 512 + tid;            // 1024 uint4 per image
            int m = idx4 >> 3, kq = idx4 & 7;
            int r = rowbase + m;
            uint4 va = make_uint4(0, 0, 0, 0), vb = make_uint4(0, 0, 0, 0);
            if (r < N_NODES) {
                va = gA4hi[(size_t)r * 16 + kq4 + kq];
                vb = gA4lo[(size_t)r * 16 + kq4 + kq];
            }
            *(uint4*)&sm32[m * 44 + kq * 4]        = va;
            *(uint4*)&sm32[5632 + m * 44 + kq * 4] = vb;
            int nrow = nh * 128 + m;
            *(uint4*)&sm32[11264 + m * 44 + kq * 4] = gB4hi[nrow * 16 + kq4 + kq];
            *(uint4*)&sm32[16896 + m * 44 + kq * 4] = gB4lo[nrow * 16 + kq4 + kq];
        }
        __syncthreads();
        #pragma unroll
        for (int ks = 0; ks < 4; ks++) {
            uint32_t a_hi[2][4], a_lo[2][4], b[2][4], bds[2];
            int arow = (lane & 7) + ((lane >> 3) & 1) * 8;
            int akoff = ks * 16 + (lane >> 4) * 8;      // bf16 units
            #pragma unroll
            for (int mf = 0; mf < 2; mf++) {
                uint32_t ad = sb + (warpM * 32 + mf * 16 + arow) * 176 + akoff * 2;
                LDSM_X4(a_hi[mf], ad);
                LDSM_X4(a_lo[mf], ad + 22528);
            }
            int brow = (lane & 7) + (lane >> 4) * 8;
            int bkoff = ks * 16 + ((lane >> 3) & 1) * 8;
            #pragma unroll
            for (int nf = 0; nf < 2; nf++) {
                bds[nf] = sb + 45056 + (warpN * 32 + nf * 16 + brow) * 176 + bkoff * 2;
                LDSM_X4(b[nf], bds[nf]);
            }
            #pragma unroll
            for (int mf = 0; mf < 2; mf++)
                #pragma unroll
                for (int nf = 0; nf < 2; nf++) {
                    MMA_BF16(acc[mf][nf * 2],     a_hi[mf], b[nf][0], b[nf][1]);
                    MMA_BF16(acc[mf][nf * 2 + 1], a_hi[mf], b[nf][2], b[nf][3]);
                    MMA_BF16(acc[mf][nf * 2],     a_lo[mf], b[nf][0], b[nf][1]);
                    MMA_BF16(acc[mf][nf * 2 + 1], a_lo[mf], b[nf][2], b[nf][3]);
                }
            #pragma unroll
            for (int nf = 0; nf < 2; nf++) LDSM_X4(b[nf], bds[nf] + 22528);
            #pragma unroll
            for (int mf = 0; mf < 2; mf++)
                #pragma unroll
                for (int nf = 0; nf < 2; nf++) {
                    MMA_BF16(acc[mf][nf * 2],     a_hi[mf], b[nf][0], b[nf][1]);
                    MMA_BF16(acc[mf][nf * 2 + 1], a_hi[mf], b[nf][2], b[nf][3]);
                }
        }
    }

    // epilogue: +b1, relu, split-store h, BN stats
    float ls[4][2], lq[4][2];
    #pragma unroll
    for (int i = 0; i < 4; i++) { ls[i][0] = ls[i][1] = lq[i][0] = lq[i][1] = 0.f; }
    int mrow = rowbase + warpM * 32 + (lane >> 2);
    #pragma unroll
    for (int nfi = 0; nfi < 4; nfi++) {
        int nl = warpN * 32 + nfi * 8 + 2 * (lane & 3);
        int ncol = nh * 128 + nl;
        float bb0 = b1g[ncol], bb1 = b1g[ncol + 1];
        #pragma unroll
        for (int mf = 0; mf < 2; mf++) {
            int m0 = mrow + mf * 16;
            float v0 = fmaxf(acc[mf][nfi][0] + bb0, 0.f);
            float v1 = fmaxf(acc[mf][nfi][1] + bb1, 0.f);
            float v2 = fmaxf(acc[mf][nfi][2] + bb0, 0.f);
            float v3 = fmaxf(acc[mf][nfi][3] + bb1, 0.f);
            if (m0 < N_NODES) {
                g_hhi[(size_t)m0 * 128 + (ncol >> 1)] = packhi2(v0, v1);
                g_hlo[(size_t)m0 * 128 + (ncol >> 1)] = packlo2(v0, v1);
                ls[nfi][0] += v0; ls[nfi][1] += v1;
                lq[nfi][0] += v0 * v0; lq[nfi][1] += v1 * v1;
            }
            if (m0 + 8 < N_NODES) {
                g_hhi[(size_t)(m0 + 8) * 128 + (ncol >> 1)] = packhi2(v2, v3);
                g_hlo[(size_t)(m0 + 8) * 128 + (ncol >> 1)] = packlo2(v2, v3);
                ls[nfi][0] += v2; ls[nfi][1] += v3;
                lq[nfi][0] += v2 * v2; lq[nfi][1] += v3 * v3;
            }
        }
    }
    #pragma unroll
    for (int nfi = 0; nfi < 4; nfi++)
        #pragma unroll
        for (int j = 0; j < 2; j++) {
            float s = ls[nfi][j], q = lq[nfi][j];
            s += __shfl_xor_sync(0xFFFFFFFFu, s, 4);
            s += __shfl_xor_sync(0xFFFFFFFFu, s, 8);
            s += __shfl_xor_sync(0xFFFFFFFFu, s, 16);
            q += __shfl_xor_sync(0xFFFFFFFFu, q, 4);
            q += __shfl_xor_sync(0xFFFFFFFFu, q, 8);
            q += __shfl_xor_sync(0xFFFFFFFFu, q, 16);
            if ((lane >> 2) == 0) {
                int col = warpN * 32 + nfi * 8 + 2 * (lane & 3) + j;
                atomicAdd(&ssum[col], s);
                atomicAdd(&ssq[col], q);
            }
        }
    __syncthreads();
    if (tid < 128) {
        atomicAdd(&P_COLSUM()[nh * 128 + tid], ssum[tid]);
        atomicAdd(&P_COLSQ()[nh * 128 + tid],  ssq[tid]);
    }
}

// ---------------- 6) finalize: BN fold -> split W2p + b2' ------------------
__global__ void finalize_kernel(const float* __restrict__ gamma,
                                const float* __restrict__ beta,
                                const float* __restrict__ W2,
                                const float* __restrict__ b2) {
    __shared__ float s_sm[MID], t_sm[MID];
    int tid = threadIdx.x;  // 256
    float mu  = P_COLSUM()[tid] * (1.f / N_NODES);
    float var = P_COLSQ()[tid]  * (1.f / N_NODES) - mu * mu;
    float s = gamma[tid] * rsqrtf(var + BN_EPS);
    float t = beta[tid] - mu * s;
    s_sm[tid] = s; t_sm[tid] = t;
    __syncthreads();
    #pragma unroll 1
    for (int i = 0; i < 32; i++) {
        int idx = i * 256 + tid;            // 8192 k-pairs
        int n = idx >> 7, kp = idx & 127;
        float v0 = W2[(size_t)(2 * kp)     * OUT_F + n] * s_sm[2 * kp];
        float v1 = W2[(size_t)(2 * kp + 1) * OUT_F + n] * s_sm[2 * kp + 1];
        g_W2phi[n * 128 + kp] = packhi2(v0, v1);
        g_W2plo[n * 128 + kp] = packlo2(v0, v1);
    }
    if (tid < OUT_F) {
        float acc = b2[tid];
        for (int j = 0; j < MID; j++) acc += t_sm[j] * W2[j * OUT_F + tid];
        g_b2p[tid] = acc;
    }
}

// ---------------- 7) GEMM2 via mma.sync bf16x3 -----------------------------
// 128m x 64n block (grid 782), 16 warps (4m x 4n), warp tile 32x16. (R13 form)
#define G2_SMEM_BYTES 67584
__global__ __launch_bounds__(512, 3)
void gemm2_tc(float* __restrict__ out) {
    extern __shared__ __align__(16) uint32_t sm32[];
    uint32_t sb = smem_u32(sm32);
    int tid = threadIdx.x;
    int wid = tid >> 5, lane = tid & 31;
    int rowbase = blockIdx.x * 128;
    int warpM = wid & 3, warpN = wid >> 2;      // 4 x 4

    const uint4* gh4hi = (const uint4*)g_hhi;
    const uint4* gh4lo = (const uint4*)g_hlo;
    const uint4* gW4hi = (const uint4*)g_W2phi;
    const uint4* gW4lo = (const uint4*)g_W2plo;

    float acc[2][2][4];
    #pragma unroll
    for (int a = 0; a < 2; a++)
        #pragma unroll
        for (int b = 0; b < 2; b++)
            #pragma unroll
            for (int c = 0; c < 4; c++) acc[a][b][c] = 0.f;

    #pragma unroll 1
    for (int kc2 = 0; kc2 < 128; kc2 += 32) {
        int kq4 = kc2 >> 2;                      // uint4 offset {0,8,16,24}
        __syncthreads();
        #pragma unroll
        for (int i = 0; i < 2; i++) {
            int idx4 = i * 512 + tid;            // A: 1024 uint4 per image
            int m = idx4 >> 3, kq = idx4 & 7;
            int r = rowbase + m;
            uint4 va = make_uint4(0, 0, 0, 0), vb = make_uint4(0, 0, 0, 0);
            if (r < N_NODES) {
                va = gh4hi[(size_t)r * 32 + kq4 + kq];
                vb = gh4lo[(size_t)r * 32 + kq4 + kq];
            }
            *(uint4*)&sm32[m * 44 + kq * 4]        = va;
            *(uint4*)&sm32[5632 + m * 44 + kq * 4] = vb;
        }
        {
            int idx4 = tid;                      // B: 512 uint4 per image
            int n = idx4 >> 3, kq = idx4 & 7;
            *(uint4*)&sm32[11264 + n * 44 + kq * 4] = gW4hi[n * 32 + kq4 + kq];
            *(uint4*)&sm32[14080 + n * 44 + kq * 4] = gW4lo[n * 32 + kq4 + kq];
        }
        __syncthreads();
        #pragma unroll
        for (int ks = 0; ks < 4; ks++) {
            uint32_t a_hi[2][4], a_lo[2][4], b[1][4], bds;
            int arow = (lane & 7) + ((lane >> 3) & 1) * 8;
            int akoff = ks * 16 + (lane >> 4) * 8;
            #pragma unroll
            for (int mf = 0; mf < 2; mf++) {
                uint32_t ad = sb + (warpM * 32 + mf * 16 + arow) * 176 + akoff * 2;
                LDSM_X4(a_hi[mf], ad);
                LDSM_X4(a_lo[mf], ad + 22528);
            }
            int brow = (lane & 7) + (lane >> 4) * 8;
            int bkoff = ks * 16 + ((lane >> 3) & 1) * 8;
            bds = sb + 45056 + (warpN * 16 + brow) * 176 + bkoff * 2;
            LDSM_X4(b[0], bds);
            #pragma unroll
            for (int mf = 0; mf < 2; mf++) {
                MMA_BF16(acc[mf][0], a_hi[mf], b[0][0], b[0][1]);
                MMA_BF16(acc[mf][1], a_hi[mf], b[0][2], b[0][3]);
                MMA_BF16(acc[mf][0], a_lo[mf], b[0][0], b[0][1]);
                MMA_BF16(acc[mf][1], a_lo[mf], b[0][2], b[0][3]);
            }
            LDSM_X4(b[0], bds + 11264);
            #pragma unroll
            for (int mf = 0; mf < 2; mf++) {
                MMA_BF16(acc[mf][0], a_hi[mf], b[0][0], b[0][1]);
                MMA_BF16(acc[mf][1], a_hi[mf], b[0][2], b[0][3]);
            }
        }
    }

    int mrow = rowbase + warpM * 32 + (lane >> 2);
    #pragma unroll
    for (int nfi = 0; nfi < 2; nfi++) {
        int nl = warpN * 16 + nfi * 8 + 2 * (lane & 3);
        float bb0 = g_b2p[nl], bb1 = g_b2p[nl + 1];
        #pragma unroll
        for (int mf = 0; mf < 2; mf++) {
            int m0 = mrow + mf * 16;
            if (m0 < N_NODES) {
                float2 o = make_float2(acc[mf][nfi][0] + bb0, acc[mf][nfi][1] + bb1);
                *(float2*)&out[(size_t)m0 * OUT_F + nl] = o;
            }
            if (m0 + 8 < N_NODES) {
                float2 o = make_float2(acc[mf][nfi][2] + bb0, acc[mf][nfi][3] + bb1);
                *(float2*)&out[(size_t)(m0 + 8) * OUT_F + nl] = o;
            }
        }
    }
}

// ---------------- launch ---------------------------------------------------
extern "C" void kernel_launch(void* const* d_in, const int* in_sizes, int n_in,
                              void* d_out, int out_size) {
    int ix = -1, iei = -1, iea = -1, iW1 = -1, iW2 = -1, ib2 = -1;
    int p256[3]; int n256 = 0;
    for (int i = 0; i < n_in; i++) {
        switch (in_sizes[i]) {
            case 6400000: ix  = i; break;
            case 2560000: iei = i; break;
            case 1280000: iea = i; break;
            case 32768:   iW1 = i; break;
            case 16384:   iW2 = i; break;
            case 64:      ib2 = i; break;
            case 256:     if (n256 < 3) p256[n256++] = i; break;
            default: break;
        }
    }
    int ib1, igamma, ibeta;
    if (n_in > 0 && in_sizes[0] == 6400000) { ib1 = p256[0]; igamma = p256[1]; ibeta = p256[2]; }
    else                                    { ib1 = p256[0]; ibeta  = p256[1]; igamma = p256[2]; }

    const float* x     = (const float*)d_in[ix];
    const void*  ei    = d_in[iei];
    const float* ea    = (const float*)d_in[iea];
    const float* W1    = (const float*)d_in[iW1];
    const float* b1    = (const float*)d_in[ib1];
    const float* gamma = (const float*)d_in[igamma];
    const float* beta  = (const float*)d_in[ibeta];
    const float* W2    = (const float*)d_in[iW2];
    const float* b2    = (const float*)d_in[ib2];
    float* out = (float*)d_out;

    cudaFuncSetAttribute(gemm1_tc, cudaFuncAttributeMaxDynamicSharedMemorySize,
                         G1_SMEM_BYTES);
    cudaFuncSetAttribute(gemm2_tc, cudaFuncAttributeMaxDynamicSharedMemorySize,
                         G2_SMEM_BYTES);

    hist_kernel<<<(E_EDGES + 255) / 256, 256>>>(ei);
    scan_kernel<<<1, 1024>>>(W1);
    scatter_kernel<<<(E_EDGES + 255) / 256, 256>>>(ei, ea);
    agg_kernel<<<(N_NODES * 32 + 255) / 256, 256>>>(x);

    dim3 g1(NTILES, 2);
    gemm1_tc<<<g1, 512, G1_SMEM_BYTES>>>(b1);
    finalize_kernel<<<1, 256>>>(gamma, beta, W2, b2);
    gemm2_tc<<<NTILES, 512, G2_SMEM_BYTES>>>(out);
}

// round 16
// speedup vs baseline: 1.2857x; 1.0969x over previous
#include <cuda_runtime.h>
#include <cuda_bf16.h>
#include <cstdint>

#define N_NODES 100000
#define E_EDGES 1280000
#define C_IN    64
#define MID     256
#define OUT_F   64
#define BN_EPS  1e-5f
#define NTILES  782            // ceil(100000/128)
#define HB      5000           // hist edge blocks (5000*256 == E)
#define WB      16             // extra blocks building W1 images

// ---------------- scratch (static device memory; zero-init at load) --------
__device__ unsigned int g_zero[2 * N_NODES + 512];
#define P_CNT()    ((int*)g_zero)
#define P_OFF()    (((int*)g_zero) + N_NODES)
#define P_COLSUM() ((float*)(((int*)g_zero) + 2 * N_NODES))
#define P_COLSQ()  ((float*)(((int*)g_zero) + 2 * N_NODES + 256))

__device__ __align__(16) int g_start[N_NODES + 4];   // CSR offsets (int4 stores)
__device__ int2  g_edge[E_EDGES];                 // row-sorted (col, attr-bits)
__device__ __nv_bfloat16 g_Ahi[(size_t)N_NODES * 128];  // agg bf16 split
__device__ __nv_bfloat16 g_Alo[(size_t)N_NODES * 128];
__device__ __nv_bfloat16 g_Bhi[256 * 128];        // W1^T bf16 split [n][k]
__device__ __nv_bfloat16 g_Blo[256 * 128];
__device__ uint32_t g_hhi[(size_t)N_NODES * 128]; // h bf16 split, packed pairs
__device__ uint32_t g_hlo[(size_t)N_NODES * 128];
__device__ uint32_t g_W2phi[64 * 128];            // W2p^T bf16 split [n][k] pairs
__device__ uint32_t g_W2plo[64 * 128];
__device__ float g_b2p[OUT_F];

// ---------------- bf16 split helpers ---------------------------------------
__device__ __forceinline__ uint32_t packhi2(float v0, float v1) {
    __nv_bfloat162 h = __floats2bfloat162_rn(v0, v1);
    return *reinterpret_cast<uint32_t*>(&h);
}
__device__ __forceinline__ uint32_t packlo2(float v0, float v1) {
    float r0 = v0 - __bfloat162float(__float2bfloat16(v0));
    float r1 = v1 - __bfloat162float(__float2bfloat16(v1));
    __nv_bfloat162 l = __floats2bfloat162_rn(r0, r1);
    return *reinterpret_cast<uint32_t*>(&l);
}

// ---------------- mma.sync helpers (sm_80+ path) ----------------------------
__device__ __forceinline__ uint32_t smem_u32(const void* p) {
    uint32_t a;
    asm("{ .reg .u64 t; cvta.to.shared.u64 t, %1; cvt.u32.u64 %0, t; }"
        : "=r"(a) : "l"(p));
    return a;
}
#define LDSM_X4(r, addr) \
    asm volatile("ldmatrix.sync.aligned.m8n8.x4.shared.b16 {%0,%1,%2,%3}, [%4];" \
        : "=r"((r)[0]), "=r"((r)[1]), "=r"((r)[2]), "=r"((r)[3]) : "r"(addr))
#define MMA_BF16(d, a, b0, b1) \
    asm volatile("mma.sync.aligned.m16n8k16.row.col.f32.bf16.bf16.f32 " \
        "{%0,%1,%2,%3}, {%4,%5,%6,%7}, {%8,%9}, {%0,%1,%2,%3};" \
        : "+f"((d)[0]), "+f"((d)[1]), "+f"((d)[2]), "+f"((d)[3]) \
        : "r"((a)[0]), "r"((a)[1]), "r"((a)[2]), "r"((a)[3]), "r"(b0), "r"(b1))

// ---------------- per-block dtype detection --------------------------------
__device__ __forceinline__ int detect_idx64_block(const int* ei32, int* sflag) {
    if (threadIdx.x == 0) {
        int all_zero = 1;
        #pragma unroll
        for (int i = 0; i < 16; i++)
            if (ei32[2 * i + 1] != 0) all_zero = 0;
        *sflag = all_zero;
    }
    __syncthreads();
    return *sflag;
}
__device__ __forceinline__ int load_idx(const void* ei, size_t pos, int idx64) {
    return idx64 ? (int)((const long long*)ei)[pos] : ((const int*)ei)[pos];
}

// ---------------- 1) histogram + W1 split-image build ----------------------
// Blocks [0, HB): edge histogram. Blocks [HB, HB+WB): W1 bf16 images
// (uncoalesced reads overlapped across 16 concurrent blocks).
__global__ void hist_kernel(const void* __restrict__ ei,
                            const float* __restrict__ W1) {
    if (blockIdx.x >= HB) {
        int b = blockIdx.x - HB;
        #pragma unroll
        for (int i = 0; i < 4; i++) {
            int idx = b * 1024 + i * 256 + threadIdx.x;   // 16384 total
            int n = idx >> 6, kp = idx & 63;
            float v0 = W1[(size_t)(2 * kp)     * MID + n];
            float v1 = W1[(size_t)(2 * kp + 1) * MID + n];
            ((uint32_t*)g_Bhi)[n * 64 + kp] = packhi2(v0, v1);
            ((uint32_t*)g_Blo)[n * 64 + kp] = packlo2(v0, v1);
        }
        return;
    }
    __shared__ int sflag;
    int idx64 = detect_idx64_block((const int*)ei, &sflag);
    int e = blockIdx.x * blockDim.x + threadIdx.x;
    int row = load_idx(ei, e, idx64);
    if ((unsigned)row < N_NODES) atomicAdd(&P_CNT()[row], 1);
}

// ---------------- 2) single-pass scan (3 phases, 2 barriers) ---------------
// Thread t owns 25 contiguous int4 (100 counts). Phase 1: local totals
// (25 loads in flight). Phase 2: block scan of 1024 totals. Phase 3: re-walk
// (L2-hot) and write int4 prefixes to g_start and P_OFF.
__global__ __launch_bounds__(1024)
void scan_kernel() {
    __shared__ int wsum[32], woff_s[32];
    int tid = threadIdx.x, lane = tid & 31, wid = tid >> 5;
    if (tid < 256) { P_COLSUM()[tid] = 0.f; P_COLSQ()[tid] = 0.f; }
    const int4* cnt4 = (const int4*)P_CNT();       // 25000 int4 exactly
    int base4 = tid * 25;
    int nown = (base4 < 25000) ? ((25000 - base4 < 25) ? 25000 - base4 : 25) : 0;
    int tot = 0;
    #pragma unroll 1
    for (int j = 0; j < nown; j++) {
        int4 v = cnt4[base4 + j];
        tot += v.x + v.y + v.z + v.w;
    }
    int p = tot;
    #pragma unroll
    for (int o = 1; o < 32; o <<= 1) {
        int t = __shfl_up_sync(0xFFFFFFFFu, p, o);
        if (lane >= o) p += t;
    }
    if (lane == 31) wsum[wid] = p;
    __syncthreads();
    if (wid == 0) {
        int t = wsum[lane];
        int q = t;
        #pragma unroll
        for (int o = 1; o < 32; o <<= 1) {
            int u = __shfl_up_sync(0xFFFFFFFFu, q, o);
            if (lane >= o) q += u;
        }
        woff_s[lane] = q - t;
    }
    __syncthreads();
    int excl = woff_s[wid] + (p - tot);
    int run = excl;
    #pragma unroll 1
    for (int j = 0; j < nown; j++) {
        int4 v = cnt4[base4 + j];
        int4 o;
        o.x = run;
        o.y = o.x + v.x;
        o.z = o.y + v.y;
        o.w = o.z + v.z;
        ((int4*)g_start)[base4 + j] = o;
        ((int4*)P_OFF())[base4 + j] = o;
        run = o.w + v.w;
    }
    if (tid == 1023) g_start[N_NODES] = excl + tot;   // trailing totals are 0
}

// ---------------- 3) scatter into row-sorted order -------------------------
__global__ void scatter_kernel(const void* __restrict__ ei,
                               const float* __restrict__ ea) {
    __shared__ int sflag;
    int idx64 = detect_idx64_block((const int*)ei, &sflag);
    int e = blockIdx.x * blockDim.x + threadIdx.x;
    if (e >= E_EDGES) return;
    int row = load_idx(ei, e, idx64);
    int col = load_idx(ei, (size_t)E_EDGES + e, idx64);
    if ((unsigned)row >= N_NODES || (unsigned)col >= N_NODES) return;
    int p = atomicAdd(&P_OFF()[row], 1);
    g_edge[p] = make_int2(col, __float_as_int(ea[e]));
}

// ---------------- 4) warp-per-node gather; float2 loads; bf16 split --------
__global__ __launch_bounds__(256)
void agg_kernel(const float* __restrict__ x) {
    int node = (blockIdx.x * blockDim.x + threadIdx.x) >> 5;
    int lane = threadIdx.x & 31;
    if (node >= N_NODES) return;
    int s = g_start[node];
    int e = g_start[node + 1];
    float vxa = 0.f, vya = 0.f, wxa = 0.f, wya = 0.f;
    float vxb = 0.f, vyb = 0.f, wxb = 0.f, wyb = 0.f;
    for (int base = s; base < e; base += 32) {
        int rem = e - base;
        int2 ed = make_int2(0, 0);
        if (lane < rem) ed = g_edge[base + lane];
        int n = rem < 32 ? rem : 32;
        int j = 0;
        #pragma unroll 1
        for (; j + 4 <= n; j += 4) {
            int   c0 = __shfl_sync(0xFFFFFFFFu, ed.x, j);
            float a0 = __int_as_float(__shfl_sync(0xFFFFFFFFu, ed.y, j));
            int   c1 = __shfl_sync(0xFFFFFFFFu, ed.x, j + 1);
            float a1 = __int_as_float(__shfl_sync(0xFFFFFFFFu, ed.y, j + 1));
            int   c2 = __shfl_sync(0xFFFFFFFFu, ed.x, j + 2);
            float a2 = __int_as_float(__shfl_sync(0xFFFFFFFFu, ed.y, j + 2));
            int   c3 = __shfl_sync(0xFFFFFFFFu, ed.x, j + 3);
            float a3 = __int_as_float(__shfl_sync(0xFFFFFFFFu, ed.y, j + 3));
            float2 p0 = *(const float2*)(x + (size_t)c0 * C_IN + 2 * lane);
            float2 p1 = *(const float2*)(x + (size_t)c1 * C_IN + 2 * lane);
            float2 p2 = *(const float2*)(x + (size_t)c2 * C_IN + 2 * lane);
            float2 p3 = *(const float2*)(x + (size_t)c3 * C_IN + 2 * lane);
            vxa += p0.x; vya += p0.y; wxa = fmaf(p0.x, a0, wxa); wya = fmaf(p0.y, a0, wya);
            vxb += p1.x; vyb += p1.y; wxb = fmaf(p1.x, a1, wxb); wyb = fmaf(p1.y, a1, wyb);
            vxa += p2.x; vya += p2.y; wxa = fmaf(p2.x, a2, wxa); wya = fmaf(p2.y, a2, wya);
            vxb += p3.x; vyb += p3.y; wxb = fmaf(p3.x, a3, wxb); wyb = fmaf(p3.y, a3, wyb);
        }
        #pragma unroll 1
        for (; j < n; j++) {
            int   c = __shfl_sync(0xFFFFFFFFu, ed.x, j);
            float a = __int_as_float(__shfl_sync(0xFFFFFFFFu, ed.y, j));
            float2 p = *(const float2*)(x + (size_t)c * C_IN + 2 * lane);
            vxa += p.x; vya += p.y;
            wxa = fmaf(p.x, a, wxa); wya = fmaf(p.y, a, wya);
        }
    }
    float inv = 1.f / fmaxf((float)(e - s), 1.f);
    float vx = (vxa + vxb) * inv, vy = (vya + vyb) * inv;
    float wx = (wxa + wxb) * inv, wy = (wya + wyb) * inv;
    uint32_t* ahi = (uint32_t*)g_Ahi;
    uint32_t* alo = (uint32_t*)g_Alo;
    size_t base = (size_t)node * 64;
    ahi[base + lane]      = packhi2(vx, vy);
    alo[base + lane]      = packlo2(vx, vy);
    ahi[base + 32 + lane] = packhi2(wx, wy);
    alo[base + 32 + lane] = packlo2(wx, wy);
}

// ---------------- 5) GEMM1 via mma.sync bf16x3 + fused BN stats ------------
// 128m x 128n block (grid 782 x 2), 16 warps (4m x 4n), warp tile 32x32.
// Pitch-44 smem images (88 KB), 2 blocks/SM. (R13/R15 proven form)
#define G1_SMEM_BYTES 90112
__global__ __launch_bounds__(512, 2)
void gemm1_tc(const float* __restrict__ b1g) {
    extern __shared__ __align__(16) uint32_t sm32[];
    uint32_t sb = smem_u32(sm32);
    __shared__ float ssum[128], ssq[128];
    int tid = threadIdx.x;
    int wid = tid >> 5, lane = tid & 31;
    int rowbase = blockIdx.x * 128;
    int nh = blockIdx.y;
    int warpM = wid & 3, warpN = wid >> 2;      // 4 x 4

    if (tid < 128) {
        ssum[tid] = 0.f; ssq[tid] = 0.f;
        int r = rowbase + tid;
        if (r < N_NODES) P_CNT()[r] = 0;    // re-zero for next graph replay
    }

    const uint4* gA4hi = (const uint4*)g_Ahi;
    const uint4* gA4lo = (const uint4*)g_Alo;
    const uint4* gB4hi = (const uint4*)g_Bhi;
    const uint4* gB4lo = (const uint4*)g_Blo;

    float acc[2][4][4];
    #pragma unroll
    for (int a = 0; a < 2; a++)
        #pragma unroll
        for (int b = 0; b < 4; b++)
            #pragma unroll
            for (int c = 0; c < 4; c++) acc[a][b][c] = 0.f;

    #pragma unroll 1
    for (int kc2 = 0; kc2 < 64; kc2 += 32) {    // k-pair (u32) chunk offset
        int kq4 = kc2 >> 2;                      // uint4 offset {0, 8}
        __syncthreads();
        #pragma unroll
        for (int i = 0; i < 2; i++) {
            int idx4 = i * 512 + tid;            // 1024 uint4 per image
            int m = idx4 >> 3, kq = idx4 & 7;
            int r = rowbase + m;
            uint4 va = make_uint4(0, 0, 0, 0), vb = make_uint4(0, 0, 0, 0);
            if (r < N_NODES) {
                va = gA4hi[(size_t)r * 16 + kq4 + kq];
                vb = gA4lo[(size_t)r * 16 + kq4 + kq];
            }
            *(uint4*)&sm32[m * 44 + kq * 4]        = va;
            *(uint4*)&sm32[5632 + m * 44 + kq * 4] = vb;
            int nrow = nh * 128 + m;
            *(uint4*)&sm32[11264 + m * 44 + kq * 4] = gB4hi[nrow * 16 + kq4 + kq];
            *(uint4*)&sm32[16896 + m * 44 + kq * 4] = gB4lo[nrow * 16 + kq4 + kq];
        }
        __syncthreads();
        #pragma unroll
        for (int ks = 0; ks < 4; ks++) {
            uint32_t a_hi[2][4], a_lo[2][4], b[2][4], bds[2];
            int arow = (lane & 7) + ((lane >> 3) & 1) * 8;
            int akoff = ks * 16 + (lane >> 4) * 8;      // bf16 units
            #pragma unroll
            for (int mf = 0; mf < 2; mf++) {
                uint32_t ad = sb + (warpM * 32 + mf * 16 + arow) * 176 + akoff * 2;
                LDSM_X4(a_hi[mf], ad);
                LDSM_X4(a_lo[mf], ad + 22528);
            }
            int brow = (lane & 7) + (lane >> 4) * 8;
            int bkoff = ks * 16 + ((lane >> 3) & 1) * 8;
            #pragma unroll
            for (int nf = 0; nf < 2; nf++) {
                bds[nf] = sb + 45056 + (warpN * 32 + nf * 16 + brow) * 176 + bkoff * 2;
                LDSM_X4(b[nf], bds[nf]);
            }
            #pragma unroll
            for (int mf = 0; mf < 2; mf++)
                #pragma unroll
                for (int nf = 0; nf < 2; nf++) {
                    MMA_BF16(acc[mf][nf * 2],     a_hi[mf], b[nf][0], b[nf][1]);
                    MMA_BF16(acc[mf][nf * 2 + 1], a_hi[mf], b[nf][2], b[nf][3]);
                    MMA_BF16(acc[mf][nf * 2],     a_lo[mf], b[nf][0], b[nf][1]);
                    MMA_BF16(acc[mf][nf * 2 + 1], a_lo[mf], b[nf][2], b[nf][3]);
                }
            #pragma unroll
            for (int nf = 0; nf < 2; nf++) LDSM_X4(b[nf], bds[nf] + 22528);
            #pragma unroll
            for (int mf = 0; mf < 2; mf++)
                #pragma unroll
                for (int nf = 0; nf < 2; nf++) {
                    MMA_BF16(acc[mf][nf * 2],     a_hi[mf], b[nf][0], b[nf][1]);
                    MMA_BF16(acc[mf][nf * 2 + 1], a_hi[mf], b[nf][2], b[nf][3]);
                }
        }
    }

    // epilogue: +b1, relu, split-store h, BN stats
    float ls[4][2], lq[4][2];
    #pragma unroll
    for (int i = 0; i < 4; i++) { ls[i][0] = ls[i][1] = lq[i][0] = lq[i][1] = 0.f; }
    int mrow = rowbase + warpM * 32 + (lane >> 2);
    #pragma unroll
    for (int nfi = 0; nfi < 4; nfi++) {
        int nl = warpN * 32 + nfi * 8 + 2 * (lane & 3);
        int ncol = nh * 128 + nl;
        float bb0 = b1g[ncol], bb1 = b1g[ncol + 1];
        #pragma unroll
        for (int mf = 0; mf < 2; mf++) {
            int m0 = mrow + mf * 16;
            float v0 = fmaxf(acc[mf][nfi][0] + bb0, 0.f);
            float v1 = fmaxf(acc[mf][nfi][1] + bb1, 0.f);
            float v2 = fmaxf(acc[mf][nfi][2] + bb0, 0.f);
            float v3 = fmaxf(acc[mf][nfi][3] + bb1, 0.f);
            if (m0 < N_NODES) {
                g_hhi[(size_t)m0 * 128 + (ncol >> 1)] = packhi2(v0, v1);
                g_hlo[(size_t)m0 * 128 + (ncol >> 1)] = packlo2(v0, v1);
                ls[nfi][0] += v0; ls[nfi][1] += v1;
                lq[nfi][0] += v0 * v0; lq[nfi][1] += v1 * v1;
            }
            if (m0 + 8 < N_NODES) {
                g_hhi[(size_t)(m0 + 8) * 128 + (ncol >> 1)] = packhi2(v2, v3);
                g_hlo[(size_t)(m0 + 8) * 128 + (ncol >> 1)] = packlo2(v2, v3);
                ls[nfi][0] += v2; ls[nfi][1] += v3;
                lq[nfi][0] += v2 * v2; lq[nfi][1] += v3 * v3;
            }
        }
    }
    #pragma unroll
    for (int nfi = 0; nfi < 4; nfi++)
        #pragma unroll
        for (int j = 0; j < 2; j++) {
            float s = ls[nfi][j], q = lq[nfi][j];
            s += __shfl_xor_sync(0xFFFFFFFFu, s, 4);
            s += __shfl_xor_sync(0xFFFFFFFFu, s, 8);
            s += __shfl_xor_sync(0xFFFFFFFFu, s, 16);
            q += __shfl_xor_sync(0xFFFFFFFFu, q, 4);
            q += __shfl_xor_sync(0xFFFFFFFFu, q, 8);
            q += __shfl_xor_sync(0xFFFFFFFFu, q, 16);
            if ((lane >> 2) == 0) {
                int col = warpN * 32 + nfi * 8 + 2 * (lane & 3) + j;
                atomicAdd(&ssum[col], s);
                atomicAdd(&ssq[col], q);
            }
        }
    __syncthreads();
    if (tid < 128) {
        atomicAdd(&P_COLSUM()[nh * 128 + tid], ssum[tid]);
        atomicAdd(&P_COLSQ()[nh * 128 + tid],  ssq[tid]);
    }
}

// ---------------- 6) finalize: BN fold -> split W2p + b2' ------------------
// W2 reads coalesced (consecutive tid -> consecutive n); scattered stores.
__global__ void finalize_kernel(const float* __restrict__ gamma,
                                const float* __restrict__ beta,
                                const float* __restrict__ W2,
                                const float* __restrict__ b2) {
    __shared__ float s_sm[MID], t_sm[MID];
    int tid = threadIdx.x;  // 256
    float mu  = P_COLSUM()[tid] * (1.f / N_NODES);
    float var = P_COLSQ()[tid]  * (1.f / N_NODES) - mu * mu;
    float s = gamma[tid] * rsqrtf(var + BN_EPS);
    float t = beta[tid] - mu * s;
    s_sm[tid] = s; t_sm[tid] = t;
    __syncthreads();
    #pragma unroll 1
    for (int i = 0; i < 32; i++) {
        int idx = i * 256 + tid;            // 8192 k-pairs
        int n = idx & 63, kp = idx >> 6;    // consecutive tid -> consecutive n
        float v0 = W2[(size_t)(2 * kp)     * OUT_F + n] * s_sm[2 * kp];
        float v1 = W2[(size_t)(2 * kp + 1) * OUT_F + n] * s_sm[2 * kp + 1];
        g_W2phi[n * 128 + kp] = packhi2(v0, v1);
        g_W2plo[n * 128 + kp] = packlo2(v0, v1);
    }
    if (tid < OUT_F) {
        float acc = b2[tid];
        for (int j = 0; j < MID; j++) acc += t_sm[j] * W2[j * OUT_F + tid];
        g_b2p[tid] = acc;
    }
}

// ---------------- 7) GEMM2 via mma.sync bf16x3 -----------------------------
// 128m x 64n block (grid 782), 16 warps (4m x 4n), warp tile 32x16.
#define G2_SMEM_BYTES 67584
__global__ __launch_bounds__(512, 3)
void gemm2_tc(float* __restrict__ out) {
    extern __shared__ __align__(16) uint32_t sm32[];
    uint32_t sb = smem_u32(sm32);
    int tid = threadIdx.x;
    int wid = tid >> 5, lane = tid & 31;
    int rowbase = blockIdx.x * 128;
    int warpM = wid & 3, warpN = wid >> 2;      // 4 x 4

    const uint4* gh4hi = (const uint4*)g_hhi;
    const uint4* gh4lo = (const uint4*)g_hlo;
    const uint4* gW4hi = (const uint4*)g_W2phi;
    const uint4* gW4lo = (const uint4*)g_W2plo;

    float acc[2][2][4];
    #pragma unroll
    for (int a = 0; a < 2; a++)
        #pragma unroll
        for (int b = 0; b < 2; b++)
            #pragma unroll
            for (int c = 0; c < 4; c++) acc[a][b][c] = 0.f;

    #pragma unroll 1
    for (int kc2 = 0; kc2 < 128; kc2 += 32) {
        int kq4 = kc2 >> 2;                      // uint4 offset {0,8,16,24}
        __syncthreads();
        #pragma unroll
        for (int i = 0; i < 2; i++) {
            int idx4 = i * 512 + tid;            // A: 1024 uint4 per image
            int m = idx4 >> 3, kq = idx4 & 7;
            int r = rowbase + m;
            uint4 va = make_uint4(0, 0, 0, 0), vb = make_uint4(0, 0, 0, 0);
            if (r < N_NODES) {
                va = gh4hi[(size_t)r * 32 + kq4 + kq];
                vb = gh4lo[(size_t)r * 32 + kq4 + kq];
            }
            *(uint4*)&sm32[m * 44 + kq * 4]        = va;
            *(uint4*)&sm32[5632 + m * 44 + kq * 4] = vb;
        }
        {
            int idx4 = tid;                      // B: 512 uint4 per image
            int n = idx4 >> 3, kq = idx4 & 7;
            *(uint4*)&sm32[11264 + n * 44 + kq * 4] = gW4hi[n * 32 + kq4 + kq];
            *(uint4*)&sm32[14080 + n * 44 + kq * 4] = gW4lo[n * 32 + kq4 + kq];
        }
        __syncthreads();
        #pragma unroll
        for (int ks = 0; ks < 4; ks++) {
            uint32_t a_hi[2][4], a_lo[2][4], b[1][4], bds;
            int arow = (lane & 7) + ((lane >> 3) & 1) * 8;
            int akoff = ks * 16 + (lane >> 4) * 8;
            #pragma unroll
            for (int mf = 0; mf < 2; mf++) {
                uint32_t ad = sb + (warpM * 32 + mf * 16 + arow) * 176 + akoff * 2;
                LDSM_X4(a_hi[mf], ad);
                LDSM_X4(a_lo[mf], ad + 22528);
            }
            int brow = (lane & 7) + (lane >> 4) * 8;
            int bkoff = ks * 16 + ((lane >> 3) & 1) * 8;
            bds = sb + 45056 + (warpN * 16 + brow) * 176 + bkoff * 2;
            LDSM_X4(b[0], bds);
            #pragma unroll
            for (int mf = 0; mf < 2; mf++) {
                MMA_BF16(acc[mf][0], a_hi[mf], b[0][0], b[0][1]);
                MMA_BF16(acc[mf][1], a_hi[mf], b[0][2], b[0][3]);
                MMA_BF16(acc[mf][0], a_lo[mf], b[0][0], b[0][1]);
                MMA_BF16(acc[mf][1], a_lo[mf], b[0][2], b[0][3]);
            }
            LDSM_X4(b[0], bds + 11264);
            #pragma unroll
            for (int mf = 0; mf < 2; mf++) {
                MMA_BF16(acc[mf][0], a_hi[mf], b[0][0], b[0][1]);
                MMA_BF16(acc[mf][1], a_hi[mf], b[0][2], b[0][3]);
            }
        }
    }

    int mrow = rowbase + warpM * 32 + (lane >> 2);
    #pragma unroll
    for (int nfi = 0; nfi < 2; nfi++) {
        int nl = warpN * 16 + nfi * 8 + 2 * (lane & 3);
        float bb0 = g_b2p[nl], bb1 = g_b2p[nl + 1];
        #pragma unroll
        for (int mf = 0; mf < 2; mf++) {
            int m0 = mrow + mf * 16;
            if (m0 < N_NODES) {
                float2 o = make_float2(acc[mf][nfi][0] + bb0, acc[mf][nfi][1] + bb1);
                *(float2*)&out[(size_t)m0 * OUT_F + nl] = o;
            }
            if (m0 + 8 < N_NODES) {
                float2 o = make_float2(acc[mf][nfi][2] + bb0, acc[mf][nfi][3] + bb1);
                *(float2*)&out[(size_t)(m0 + 8) * OUT_F + nl] = o;
            }
        }
    }
}

// ---------------- launch ---------------------------------------------------
extern "C" void kernel_launch(void* const* d_in, const int* in_sizes, int n_in,
                              void* d_out, int out_size) {
    int ix = -1, iei = -1, iea = -1, iW1 = -1, iW2 = -1, ib2 = -1;
    int p256[3]; int n256 = 0;
    for (int i = 0; i < n_in; i++) {
        switch (in_sizes[i]) {
            case 6400000: ix  = i; break;
            case 2560000: iei = i; break;
            case 1280000: iea = i; break;
            case 32768:   iW1 = i; break;
            case 16384:   iW2 = i; break;
            case 64:      ib2 = i; break;
            case 256:     if (n256 < 3) p256[n256++] = i; break;
            default: break;
        }
    }
    int ib1, igamma, ibeta;
    if (n_in > 0 && in_sizes[0] == 6400000) { ib1 = p256[0]; igamma = p256[1]; ibeta = p256[2]; }
    else                                    { ib1 = p256[0]; ibeta  = p256[1]; igamma = p256[2]; }

    const float* x     = (const float*)d_in[ix];
    const void*  ei    = d_in[iei];
    const float* ea    = (const float*)d_in[iea];
    const float* W1    = (const float*)d_in[iW1];
    const float* b1    = (const float*)d_in[ib1];
    const float* gamma = (const float*)d_in[igamma];
    const float* beta  = (const float*)d_in[ibeta];
    const float* W2    = (const float*)d_in[iW2];
    const float* b2    = (const float*)d_in[ib2];
    float* out = (float*)d_out;

    cudaFuncSetAttribute(gemm1_tc, cudaFuncAttributeMaxDynamicSharedMemorySize,
                         G1_SMEM_BYTES);
    cudaFuncSetAttribute(gemm2_tc, cudaFuncAttributeMaxDynamicSharedMemorySize,
                         G2_SMEM_BYTES);

    hist_kernel<<<HB + WB, 256>>>(ei, W1);
    scan_kernel<<<1, 1024>>>();
    scatter_kernel<<<(E_EDGES + 255) / 256, 256>>>(ei, ea);
    agg_kernel<<<(N_NODES * 32 + 255) / 256, 256>>>(x);

    dim3 g1(NTILES, 2);
    gemm1_tc<<<g1, 512, G1_SMEM_BYTES>>>(b1);
    finalize_kernel<<<1, 256>>>(gamma, beta, W2, b2);
    gemm2_tc<<<NTILES, 512, G2_SMEM_BYTES>>>(out);
}

// round 17
// speedup vs baseline: 1.2927x; 1.0055x over previous
#include <cuda_runtime.h>
#include <cuda_bf16.h>
#include <cstdint>

#define N_NODES 100000
#define E_EDGES 1280000
#define C_IN    64
#define MID     256
#define OUT_F   64
#define BN_EPS  1e-5f
#define NTILES  782            // ceil(100000/128)
#define HB      5000           // hist edge blocks (5000*256 == E)
#define WB      16             // extra blocks building W1 images

// ---------------- scratch (static device memory; zero-init at load) --------
__device__ unsigned int g_zero[2 * N_NODES + 512];
#define P_CNT()    ((int*)g_zero)
#define P_OFF()    (((int*)g_zero) + N_NODES)
#define P_COLSUM() ((float*)(((int*)g_zero) + 2 * N_NODES))
#define P_COLSQ()  ((float*)(((int*)g_zero) + 2 * N_NODES + 256))

__device__ __align__(16) int g_start[N_NODES + 4];   // CSR offsets (int4 stores)
__device__ int2  g_edge[E_EDGES];                 // row-sorted (col, attr-bits)
__device__ __nv_bfloat16 g_Ahi[(size_t)N_NODES * 128];  // agg bf16 split
__device__ __nv_bfloat16 g_Alo[(size_t)N_NODES * 128];
__device__ __nv_bfloat16 g_Bhi[256 * 128];        // W1^T bf16 split [n][k]
__device__ __nv_bfloat16 g_Blo[256 * 128];
__device__ uint32_t g_hhi[(size_t)N_NODES * 128]; // h bf16 split, packed pairs
__device__ uint32_t g_hlo[(size_t)N_NODES * 128];
__device__ uint32_t g_W2phi[64 * 128];            // W2p^T bf16 split [n][k] pairs
__device__ uint32_t g_W2plo[64 * 128];
__device__ float g_b2p[OUT_F];

// ---------------- bf16 split helpers ---------------------------------------
__device__ __forceinline__ uint32_t packhi2(float v0, float v1) {
    __nv_bfloat162 h = __floats2bfloat162_rn(v0, v1);
    return *reinterpret_cast<uint32_t*>(&h);
}
__device__ __forceinline__ uint32_t packlo2(float v0, float v1) {
    float r0 = v0 - __bfloat162float(__float2bfloat16(v0));
    float r1 = v1 - __bfloat162float(__float2bfloat16(v1));
    __nv_bfloat162 l = __floats2bfloat162_rn(r0, r1);
    return *reinterpret_cast<uint32_t*>(&l);
}

// ---------------- mma.sync + cp.async helpers (sm_80+ path) -----------------
__device__ __forceinline__ uint32_t smem_u32(const void* p) {
    uint32_t a;
    asm("{ .reg .u64 t; cvta.to.shared.u64 t, %1; cvt.u32.u64 %0, t; }"
        : "=r"(a) : "l"(p));
    return a;
}
#define LDSM_X4(r, addr) \
    asm volatile("ldmatrix.sync.aligned.m8n8.x4.shared.b16 {%0,%1,%2,%3}, [%4];" \
        : "=r"((r)[0]), "=r"((r)[1]), "=r"((r)[2]), "=r"((r)[3]) : "r"(addr))
#define MMA_BF16(d, a, b0, b1) \
    asm volatile("mma.sync.aligned.m16n8k16.row.col.f32.bf16.bf16.f32 " \
        "{%0,%1,%2,%3}, {%4,%5,%6,%7}, {%8,%9}, {%0,%1,%2,%3};" \
        : "+f"((d)[0]), "+f"((d)[1]), "+f"((d)[2]), "+f"((d)[3]) \
        : "r"((a)[0]), "r"((a)[1]), "r"((a)[2]), "r"((a)[3]), "r"(b0), "r"(b1))
#define CP_A16(saddr, gptr, sz) \
    asm volatile("cp.async.cg.shared.global [%0], [%1], 16, %2;" \
        :: "r"(saddr), "l"(gptr), "r"(sz) : "memory")
#define CP_COMMIT() asm volatile("cp.async.commit_group;" ::: "memory")
#define CP_WAIT0()  asm volatile("cp.async.wait_group 0;" ::: "memory")

// ---------------- per-block dtype detection --------------------------------
__device__ __forceinline__ int detect_idx64_block(const int* ei32, int* sflag) {
    if (threadIdx.x == 0) {
        int all_zero = 1;
        #pragma unroll
        for (int i = 0; i < 16; i++)
            if (ei32[2 * i + 1] != 0) all_zero = 0;
        *sflag = all_zero;
    }
    __syncthreads();
    return *sflag;
}
__device__ __forceinline__ int load_idx(const void* ei, size_t pos, int idx64) {
    return idx64 ? (int)((const long long*)ei)[pos] : ((const int*)ei)[pos];
}

// ---------------- 1) histogram + W1 split-image build ----------------------
__global__ void hist_kernel(const void* __restrict__ ei,
                            const float* __restrict__ W1) {
    if (blockIdx.x >= HB) {
        int b = blockIdx.x - HB;
        #pragma unroll
        for (int i = 0; i < 4; i++) {
            int idx = b * 1024 + i * 256 + threadIdx.x;   // 16384 total
            int n = idx >> 6, kp = idx & 63;
            float v0 = W1[(size_t)(2 * kp)     * MID + n];
            float v1 = W1[(size_t)(2 * kp + 1) * MID + n];
            ((uint32_t*)g_Bhi)[n * 64 + kp] = packhi2(v0, v1);
            ((uint32_t*)g_Blo)[n * 64 + kp] = packlo2(v0, v1);
        }
        return;
    }
    __shared__ int sflag;
    int idx64 = detect_idx64_block((const int*)ei, &sflag);
    int e = blockIdx.x * blockDim.x + threadIdx.x;
    int row = load_idx(ei, e, idx64);
    if ((unsigned)row < N_NODES) atomicAdd(&P_CNT()[row], 1);
}

// ---------------- 2) single-pass scan (3 phases, 2 barriers) ---------------
__global__ __launch_bounds__(1024)
void scan_kernel() {
    __shared__ int wsum[32], woff_s[32];
    int tid = threadIdx.x, lane = tid & 31, wid = tid >> 5;
    if (tid < 256) { P_COLSUM()[tid] = 0.f; P_COLSQ()[tid] = 0.f; }
    const int4* cnt4 = (const int4*)P_CNT();       // 25000 int4 exactly
    int base4 = tid * 25;
    int nown = (base4 < 25000) ? ((25000 - base4 < 25) ? 25000 - base4 : 25) : 0;
    int tot = 0;
    #pragma unroll 1
    for (int j = 0; j < nown; j++) {
        int4 v = cnt4[base4 + j];
        tot += v.x + v.y + v.z + v.w;
    }
    int p = tot;
    #pragma unroll
    for (int o = 1; o < 32; o <<= 1) {
        int t = __shfl_up_sync(0xFFFFFFFFu, p, o);
        if (lane >= o) p += t;
    }
    if (lane == 31) wsum[wid] = p;
    __syncthreads();
    if (wid == 0) {
        int t = wsum[lane];
        int q = t;
        #pragma unroll
        for (int o = 1; o < 32; o <<= 1) {
            int u = __shfl_up_sync(0xFFFFFFFFu, q, o);
            if (lane >= o) q += u;
        }
        woff_s[lane] = q - t;
    }
    __syncthreads();
    int excl = woff_s[wid] + (p - tot);
    int run = excl;
    #pragma unroll 1
    for (int j = 0; j < nown; j++) {
        int4 v = cnt4[base4 + j];
        int4 o;
        o.x = run;
        o.y = o.x + v.x;
        o.z = o.y + v.y;
        o.w = o.z + v.z;
        ((int4*)g_start)[base4 + j] = o;
        ((int4*)P_OFF())[base4 + j] = o;
        run = o.w + v.w;
    }
    if (tid == 1023) g_start[N_NODES] = excl + tot;   // trailing totals are 0
}

// ---------------- 3) scatter into row-sorted order -------------------------
__global__ void scatter_kernel(const void* __restrict__ ei,
                               const float* __restrict__ ea) {
    __shared__ int sflag;
    int idx64 = detect_idx64_block((const int*)ei, &sflag);
    int e = blockIdx.x * blockDim.x + threadIdx.x;
    if (e >= E_EDGES) return;
    int row = load_idx(ei, e, idx64);
    int col = load_idx(ei, (size_t)E_EDGES + e, idx64);
    if ((unsigned)row >= N_NODES || (unsigned)col >= N_NODES) return;
    int p = atomicAdd(&P_OFF()[row], 1);
    g_edge[p] = make_int2(col, __float_as_int(ea[e]));
}

// ---------------- 4) warp-per-node gather; uniform edge loads --------------
// All lanes load g_edge[i] (warp-uniform -> L1 broadcast); lane owns feature
// pair (2*lane, 2*lane+1) via one LDG.64 per edge.
__global__ __launch_bounds__(256)
void agg_kernel(const float* __restrict__ x) {
    int node = (blockIdx.x * blockDim.x + threadIdx.x) >> 5;
    int lane = threadIdx.x & 31;
    if (node >= N_NODES) return;
    int s = g_start[node];
    int e = g_start[node + 1];
    float vxa = 0.f, vya = 0.f, wxa = 0.f, wya = 0.f;
    float vxb = 0.f, vyb = 0.f, wxb = 0.f, wyb = 0.f;
    int i = s;
    #pragma unroll 1
    for (; i + 4 <= e; i += 4) {
        int2 e0 = g_edge[i];
        int2 e1 = g_edge[i + 1];
        int2 e2 = g_edge[i + 2];
        int2 e3 = g_edge[i + 3];
        float a0 = __int_as_float(e0.y);
        float a1 = __int_as_float(e1.y);
        float a2 = __int_as_float(e2.y);
        float a3 = __int_as_float(e3.y);
        float2 p0 = *(const float2*)(x + (size_t)e0.x * C_IN + 2 * lane);
        float2 p1 = *(const float2*)(x + (size_t)e1.x * C_IN + 2 * lane);
        float2 p2 = *(const float2*)(x + (size_t)e2.x * C_IN + 2 * lane);
        float2 p3 = *(const float2*)(x + (size_t)e3.x * C_IN + 2 * lane);
        vxa += p0.x; vya += p0.y; wxa = fmaf(p0.x, a0, wxa); wya = fmaf(p0.y, a0, wya);
        vxb += p1.x; vyb += p1.y; wxb = fmaf(p1.x, a1, wxb); wyb = fmaf(p1.y, a1, wyb);
        vxa += p2.x; vya += p2.y; wxa = fmaf(p2.x, a2, wxa); wya = fmaf(p2.y, a2, wya);
        vxb += p3.x; vyb += p3.y; wxb = fmaf(p3.x, a3, wxb); wyb = fmaf(p3.y, a3, wyb);
    }
    #pragma unroll 1
    for (; i < e; i++) {
        int2 ed = g_edge[i];
        float a = __int_as_float(ed.y);
        float2 p = *(const float2*)(x + (size_t)ed.x * C_IN + 2 * lane);
        vxa += p.x; vya += p.y;
        wxa = fmaf(p.x, a, wxa); wya = fmaf(p.y, a, wya);
    }
    float inv = 1.f / fmaxf((float)(e - s), 1.f);
    float vx = (vxa + vxb) * inv, vy = (vya + vyb) * inv;
    float wx = (wxa + wxb) * inv, wy = (wya + wyb) * inv;
    uint32_t* ahi = (uint32_t*)g_Ahi;
    uint32_t* alo = (uint32_t*)g_Alo;
    size_t base = (size_t)node * 64;
    ahi[base + lane]      = packhi2(vx, vy);
    alo[base + lane]      = packlo2(vx, vy);
    ahi[base + 32 + lane] = packhi2(wx, wy);
    alo[base + 32 + lane] = packlo2(wx, wy);
}

// ---------------- 5) GEMM1 via mma.sync bf16x3 + fused BN stats ------------
// 128m x 128n block (grid 782 x 2), 16 warps (4m x 4n), warp tile 32x32.
// cp.async staging (zero-fill for pad rows). Pitch-44 images, 2 blocks/SM.
#define G1_SMEM_BYTES 90112
__global__ __launch_bounds__(512, 2)
void gemm1_tc(const float* __restrict__ b1g) {
    extern __shared__ __align__(16) uint32_t sm32[];
    uint32_t sb = smem_u32(sm32);
    __shared__ float ssum[128], ssq[128];
    int tid = threadIdx.x;
    int wid = tid >> 5, lane = tid & 31;
    int rowbase = blockIdx.x * 128;
    int nh = blockIdx.y;
    int warpM = wid & 3, warpN = wid >> 2;      // 4 x 4

    if (tid < 128) {
        ssum[tid] = 0.f; ssq[tid] = 0.f;
        int r = rowbase + tid;
        if (r < N_NODES) P_CNT()[r] = 0;    // re-zero for next graph replay
    }

    const uint4* gA4hi = (const uint4*)g_Ahi;
    const uint4* gA4lo = (const uint4*)g_Alo;
    const uint4* gB4hi = (const uint4*)g_Bhi;
    const uint4* gB4lo = (const uint4*)g_Blo;

    float acc[2][4][4];
    #pragma unroll
    for (int a = 0; a < 2; a++)
        #pragma unroll
        for (int b = 0; b < 4; b++)
            #pragma unroll
            for (int c = 0; c < 4; c++) acc[a][b][c] = 0.f;

    #pragma unroll 1
    for (int kc2 = 0; kc2 < 64; kc2 += 32) {    // k-pair (u32) chunk offset
        int kq4 = kc2 >> 2;                      // uint4 offset {0, 8}
        __syncthreads();
        #pragma unroll
        for (int i = 0; i < 2; i++) {
            int idx4 = i * 512 + tid;            // 1024 uint4 per image
            int m = idx4 >> 3, kq = idx4 & 7;
            int r = rowbase + m;
            int sz = (r < N_NODES) ? 16 : 0;
            size_t ga = (size_t)r * 16 + kq4 + kq;
            CP_A16(sb + (m * 44 + kq * 4) * 4,           gA4hi + ga, sz);
            CP_A16(sb + (5632 + m * 44 + kq * 4) * 4,    gA4lo + ga, sz);
            int nrow = nh * 128 + m;
            CP_A16(sb + (11264 + m * 44 + kq * 4) * 4,   gB4hi + nrow * 16 + kq4 + kq, 16);
            CP_A16(sb + (16896 + m * 44 + kq * 4) * 4,   gB4lo + nrow * 16 + kq4 + kq, 16);
        }
        CP_COMMIT();
        CP_WAIT0();
        __syncthreads();
        #pragma unroll
        for (int ks = 0; ks < 4; ks++) {
            uint32_t a_hi[2][4], a_lo[2][4], b[2][4], bds[2];
            int arow = (lane & 7) + ((lane >> 3) & 1) * 8;
            int akoff = ks * 16 + (lane >> 4) * 8;      // bf16 units
            #pragma unroll
            for (int mf = 0; mf < 2; mf++) {
                uint32_t ad = sb + (warpM * 32 + mf * 16 + arow) * 176 + akoff * 2;
                LDSM_X4(a_hi[mf], ad);
                LDSM_X4(a_lo[mf], ad + 22528);
            }
            int brow = (lane & 7) + (lane >> 4) * 8;
            int bkoff = ks * 16 + ((lane >> 3) & 1) * 8;
            #pragma unroll
            for (int nf = 0; nf < 2; nf++) {
                bds[nf] = sb + 45056 + (warpN * 32 + nf * 16 + brow) * 176 + bkoff * 2;
                LDSM_X4(b[nf], bds[nf]);
            }
            #pragma unroll
            for (int mf = 0; mf < 2; mf++)
                #pragma unroll
                for (int nf = 0; nf < 2; nf++) {
                    MMA_BF16(acc[mf][nf * 2],     a_hi[mf], b[nf][0], b[nf][1]);
                    MMA_BF16(acc[mf][nf * 2 + 1], a_hi[mf], b[nf][2], b[nf][3]);
                    MMA_BF16(acc[mf][nf * 2],     a_lo[mf], b[nf][0], b[nf][1]);
                    MMA_BF16(acc[mf][nf * 2 + 1], a_lo[mf], b[nf][2], b[nf][3]);
                }
            #pragma unroll
            for (int nf = 0; nf < 2; nf++) LDSM_X4(b[nf], bds[nf] + 22528);
            #pragma unroll
            for (int mf = 0; mf < 2; mf++)
                #pragma unroll
                for (int nf = 0; nf < 2; nf++) {
                    MMA_BF16(acc[mf][nf * 2],     a_hi[mf], b[nf][0], b[nf][1]);
                    MMA_BF16(acc[mf][nf * 2 + 1], a_hi[mf], b[nf][2], b[nf][3]);
                }
        }
    }

    // epilogue: +b1, relu, split-store h, BN stats
    float ls[4][2], lq[4][2];
    #pragma unroll
    for (int i = 0; i < 4; i++) { ls[i][0] = ls[i][1] = lq[i][0] = lq[i][1] = 0.f; }
    int mrow = rowbase + warpM * 32 + (lane >> 2);
    #pragma unroll
    for (int nfi = 0; nfi < 4; nfi++) {
        int nl = warpN * 32 + nfi * 8 + 2 * (lane & 3);
        int ncol = nh * 128 + nl;
        float bb0 = b1g[ncol], bb1 = b1g[ncol + 1];
        #pragma unroll
        for (int mf = 0; mf < 2; mf++) {
            int m0 = mrow + mf * 16;
            float v0 = fmaxf(acc[mf][nfi][0] + bb0, 0.f);
            float v1 = fmaxf(acc[mf][nfi][1] + bb1, 0.f);
            float v2 = fmaxf(acc[mf][nfi][2] + bb0, 0.f);
            float v3 = fmaxf(acc[mf][nfi][3] + bb1, 0.f);
            if (m0 < N_NODES) {
                g_hhi[(size_t)m0 * 128 + (ncol >> 1)] = packhi2(v0, v1);
                g_hlo[(size_t)m0 * 128 + (ncol >> 1)] = packlo2(v0, v1);
                ls[nfi][0] += v0; ls[nfi][1] += v1;
                lq[nfi][0] += v0 * v0; lq[nfi][1] += v1 * v1;
            }
            if (m0 + 8 < N_NODES) {
                g_hhi[(size_t)(m0 + 8) * 128 + (ncol >> 1)] = packhi2(v2, v3);
                g_hlo[(size_t)(m0 + 8) * 128 + (ncol >> 1)] = packlo2(v2, v3);
                ls[nfi][0] += v2; ls[nfi][1] += v3;
                lq[nfi][0] += v2 * v2; lq[nfi][1] += v3 * v3;
            }
        }
    }
    #pragma unroll
    for (int nfi = 0; nfi < 4; nfi++)
        #pragma unroll
        for (int j = 0; j < 2; j++) {
            float s = ls[nfi][j], q = lq[nfi][j];
            s += __shfl_xor_sync(0xFFFFFFFFu, s, 4);
            s += __shfl_xor_sync(0xFFFFFFFFu, s, 8);
            s += __shfl_xor_sync(0xFFFFFFFFu, s, 16);
            q += __shfl_xor_sync(0xFFFFFFFFu, q, 4);
            q += __shfl_xor_sync(0xFFFFFFFFu, q, 8);
            q += __shfl_xor_sync(0xFFFFFFFFu, q, 16);
            if ((lane >> 2) == 0) {
                int col = warpN * 32 + nfi * 8 + 2 * (lane & 3) + j;
                atomicAdd(&ssum[col], s);
                atomicAdd(&ssq[col], q);
            }
        }
    __syncthreads();
    if (tid < 128) {
        atomicAdd(&P_COLSUM()[nh * 128 + tid], ssum[tid]);
        atomicAdd(&P_COLSQ()[nh * 128 + tid],  ssq[tid]);
    }
}

// ---------------- 6) finalize: BN fold -> split W2p + b2' ------------------
__global__ void finalize_kernel(const float* __restrict__ gamma,
                                const float* __restrict__ beta,
                                const float* __restrict__ W2,
                                const float* __restrict__ b2) {
    __shared__ float s_sm[MID], t_sm[MID];
    int tid = threadIdx.x;  // 256
    float mu  = P_COLSUM()[tid] * (1.f / N_NODES);
    float var = P_COLSQ()[tid]  * (1.f / N_NODES) - mu * mu;
    float s = gamma[tid] * rsqrtf(var + BN_EPS);
    float t = beta[tid] - mu * s;
    s_sm[tid] = s; t_sm[tid] = t;
    __syncthreads();
    #pragma unroll 1
    for (int i = 0; i < 32; i++) {
        int idx = i * 256 + tid;            // 8192 k-pairs
        int n = idx & 63, kp = idx >> 6;    // consecutive tid -> consecutive n
        float v0 = W2[(size_t)(2 * kp)     * OUT_F + n] * s_sm[2 * kp];
        float v1 = W2[(size_t)(2 * kp + 1) * OUT_F + n] * s_sm[2 * kp + 1];
        g_W2phi[n * 128 + kp] = packhi2(v0, v1);
        g_W2plo[n * 128 + kp] = packlo2(v0, v1);
    }
    if (tid < OUT_F) {
        float acc = b2[tid];
        for (int j = 0; j < MID; j++) acc += t_sm[j] * W2[j * OUT_F + tid];
        g_b2p[tid] = acc;
    }
}

// ---------------- 7) GEMM2 via mma.sync bf16x3 -----------------------------
// 128m x 64n block (grid 782), 16 warps (4m x 4n), warp tile 32x16.
// cp.async staging. smem 66 KB, 3 blocks/SM.
#define G2_SMEM_BYTES 67584
__global__ __launch_bounds__(512, 3)
void gemm2_tc(float* __restrict__ out) {
    extern __shared__ __align__(16) uint32_t sm32[];
    uint32_t sb = smem_u32(sm32);
    int tid = threadIdx.x;
    int wid = tid >> 5, lane = tid & 31;
    int rowbase = blockIdx.x * 128;
    int warpM = wid & 3, warpN = wid >> 2;      // 4 x 4

    const uint4* gh4hi = (const uint4*)g_hhi;
    const uint4* gh4lo = (const uint4*)g_hlo;
    const uint4* gW4hi = (const uint4*)g_W2phi;
    const uint4* gW4lo = (const uint4*)g_W2plo;

    float acc[2][2][4];
    #pragma unroll
    for (int a = 0; a < 2; a++)
        #pragma unroll
        for (int b = 0; b < 2; b++)
            #pragma unroll
            for (int c = 0; c < 4; c++) acc[a][b][c] = 0.f;

    #pragma unroll 1
    for (int kc2 = 0; kc2 < 128; kc2 += 32) {
        int kq4 = kc2 >> 2;                      // uint4 offset {0,8,16,24}
        __syncthreads();
        #pragma unroll
        for (int i = 0; i < 2; i++) {
            int idx4 = i * 512 + tid;            // A: 1024 uint4 per image
            int m = idx4 >> 3, kq = idx4 & 7;
            int r = rowbase + m;
            int sz = (r < N_NODES) ? 16 : 0;
            size_t ga = (size_t)r * 32 + kq4 + kq;
            CP_A16(sb + (m * 44 + kq * 4) * 4,        gh4hi + ga, sz);
            CP_A16(sb + (5632 + m * 44 + kq * 4) * 4, gh4lo + ga, sz);
        }
        {
            int n = tid >> 3, kq = tid & 7;      // B: 512 uint4 per image
            CP_A16(sb + (11264 + n * 44 + kq * 4) * 4, gW4hi + n * 32 + kq4 + kq, 16);
            CP_A16(sb + (14080 + n * 44 + kq * 4) * 4, gW4lo + n * 32 + kq4 + kq, 16);
        }
        CP_COMMIT();
        CP_WAIT0();
        __syncthreads();
        #pragma unroll
        for (int ks = 0; ks < 4; ks++) {
            uint32_t a_hi[2][4], a_lo[2][4], b[1][4], bds;
            int arow = (lane & 7) + ((lane >> 3) & 1) * 8;
            int akoff = ks * 16 + (lane >> 4) * 8;
            #pragma unroll
            for (int mf = 0; mf < 2; mf++) {
                uint32_t ad = sb + (warpM * 32 + mf * 16 + arow) * 176 + akoff * 2;
                LDSM_X4(a_hi[mf], ad);
                LDSM_X4(a_lo[mf], ad + 22528);
            }
            int brow = (lane & 7) + (lane >> 4) * 8;
            int bkoff = ks * 16 + ((lane >> 3) & 1) * 8;
            bds = sb + 45056 + (warpN * 16 + brow) * 176 + bkoff * 2;
            LDSM_X4(b[0], bds);
            #pragma unroll
            for (int mf = 0; mf < 2; mf++) {
                MMA_BF16(acc[mf][0], a_hi[mf], b[0][0], b[0][1]);
                MMA_BF16(acc[mf][1], a_hi[mf], b[0][2], b[0][3]);
                MMA_BF16(acc[mf][0], a_lo[mf], b[0][0], b[0][1]);
                MMA_BF16(acc[mf][1], a_lo[mf], b[0][2], b[0][3]);
            }
            LDSM_X4(b[0], bds + 11264);
            #pragma unroll
            for (int mf = 0; mf < 2; mf++) {
                MMA_BF16(acc[mf][0], a_hi[mf], b[0][0], b[0][1]);
                MMA_BF16(acc[mf][1], a_hi[mf], b[0][2], b[0][3]);
            }
        }
    }

    int mrow = rowbase + warpM * 32 + (lane >> 2);
    #pragma unroll
    for (int nfi = 0; nfi < 2; nfi++) {
        int nl = warpN * 16 + nfi * 8 + 2 * (lane & 3);
        float bb0 = g_b2p[nl], bb1 = g_b2p[nl + 1];
        #pragma unroll
        for (int mf = 0; mf < 2; mf++) {
            int m0 = mrow + mf * 16;
            if (m0 < N_NODES) {
                float2 o = make_float2(acc[mf][nfi][0] + bb0, acc[mf][nfi][1] + bb1);
                *(float2*)&out[(size_t)m0 * OUT_F + nl] = o;
            }
            if (m0 + 8 < N_NODES) {
                float2 o = make_float2(acc[mf][nfi][2] + bb0, acc[mf][nfi][3] + bb1);
                *(float2*)&out[(size_t)(m0 + 8) * OUT_F + nl] = o;
            }
        }
    }
}

// ---------------- launch ---------------------------------------------------
extern "C" void kernel_launch(void* const* d_in, const int* in_sizes, int n_in,
                              void* d_out, int out_size) {
    int ix = -1, iei = -1, iea = -1, iW1 = -1, iW2 = -1, ib2 = -1;
    int p256[3]; int n256 = 0;
    for (int i = 0; i < n_in; i++) {
        switch (in_sizes[i]) {
            case 6400000: ix  = i; break;
            case 2560000: iei = i; break;
            case 1280000: iea = i; break;
            case 32768:   iW1 = i; break;
            case 16384:   iW2 = i; break;
            case 64:      ib2 = i; break;
            case 256:     if (n256 < 3) p256[n256++] = i; break;
            default: break;
        }
    }
    int ib1, igamma, ibeta;
    if (n_in > 0 && in_sizes[0] == 6400000) { ib1 = p256[0]; igamma = p256[1]; ibeta = p256[2]; }
    else                                    { ib1 = p256[0]; ibeta  = p256[1]; igamma = p256[2]; }

    const float* x     = (const float*)d_in[ix];
    const void*  ei    = d_in[iei];
    const float* ea    = (const float*)d_in[iea];
    const float* W1    = (const float*)d_in[iW1];
    const float* b1    = (const float*)d_in[ib1];
    const float* gamma = (const float*)d_in[igamma];
    const float* beta  = (const float*)d_in[ibeta];
    const float* W2    = (const float*)d_in[iW2];
    const float* b2    = (const float*)d_in[ib2];
    float* out = (float*)d_out;

    cudaFuncSetAttribute(gemm1_tc, cudaFuncAttributeMaxDynamicSharedMemorySize,
                         G1_SMEM_BYTES);
    cudaFuncSetAttribute(gemm2_tc, cudaFuncAttributeMaxDynamicSharedMemorySize,
                         G2_SMEM_BYTES);

    hist_kernel<<<HB + WB, 256>>>(ei, W1);
    scan_kernel<<<1, 1024>>>();
    scatter_kernel<<<(E_EDGES + 255) / 256, 256>>>(ei, ea);
    agg_kernel<<<(N_NODES * 32 + 255) / 256, 256>>>(x);

    dim3 g1(NTILES, 2);
    gemm1_tc<<<g1, 512, G1_SMEM_BYTES>>>(b1);
    finalize_kernel<<<1, 256>>>(gamma, beta, W2, b2);
    gemm2_tc<<<NTILES, 512, G2_SMEM_BYTES>>>(out);
}